// round 8
// baseline (speedup 1.0000x reference)
#include <cuda_runtime.h>

#define NB   148
#define NT   256
#define Bz   64
#define Tz   512
#define Cz   512
#define Hz   512
#define PINK 160
#define PINNER 256
#define CCH  32
#define KW   31
#define DRF  160
#define G3H  1536

// ---------------- scratch (static device globals; no allocation) ----------------
__device__ float g_pm[Bz * Hz * Tz];          // pm transposed: [b][h][t]
__device__ float g_h0[Bz * Hz];
__device__ float g_h1[Bz * Hz];
__device__ float g_att_sum[Bz * Tz];
__device__ float g_att_prev0[Bz * Tz];
__device__ int   g_len[Bz];
__device__ float g_dec[Bz * Hz];
__device__ float g_x1[Bz * PINNER];
__device__ float g_x2[Bz * Hz];
__device__ float g_attc[Bz * Cz];
__device__ float g_erg[Bz * Tz];
__device__ float g_gi0[Bz * G3H];
__device__ float g_gh0[Bz * G3H];
__device__ float g_gi1[Bz * G3H];
__device__ float g_gh1[Bz * G3H];
__device__ float g_opart[4 * Bz * DRF];       // out-layer K-chunk partial sums
__device__ unsigned g_barctr;

struct Params {
    const float *enc;
    const float *pn_w1, *pn_b1, *pn_w2, *pn_b2;
    const float *att_dec_w, *att_conv_w, *att_loc_w, *att_v_w;
    const float *g0_wih, *g0_whh, *g0_bih, *g0_bhh;
    const float *g1_wih, *g1_whh, *g1_bih, *g1_bhh;
    const float *out_w, *out_b;
    float *outp, *attw;
};

// ---------------- math helpers ----------------
__device__ __forceinline__ float ftanh(float x) {
    float ax = fabsf(x);
    float e  = __expf(-2.0f * ax);
    float r  = __fdividef(1.0f - e, 1.0f + e);
    return copysignf(r, x);
}
__device__ __forceinline__ float fsigm(float x) {
    return __fdividef(1.0f, 1.0f + __expf(-x));
}

// ---------------- software grid barrier (all NB blocks co-resident) ----------------
__device__ __forceinline__ void gridbar(unsigned& bno) {
    __threadfence();                 // publish this thread's stores device-wide
    __syncthreads();
    bno++;
    if (threadIdx.x == 0) {
        atomicAdd(&g_barctr, 1u);
        unsigned target = bno * NB;
        volatile unsigned* ctr = &g_barctr;
        while (*ctr < target) __nanosleep(64);
    }
    __syncthreads();
}

// ---------------- reset (graph node 1) ----------------
__global__ void reset_kernel(const int* __restrict__ dl, const float* __restrict__ outb) {
    int idx = blockIdx.x * blockDim.x + threadIdx.x;   // 64*512 = 32768
    int b = idx >> 9, t = idx & 511;
    int len = dl[b] >> 1;
    g_att_sum[idx]   = 0.0f;
    g_att_prev0[idx] = (t < len) ? (1.0f / (float)len) : 0.0f;
    g_h0[idx] = 0.0f;
    g_h1[idx] = 0.0f;
    if (idx < Bz) g_len[idx] = dl[idx] >> 1;           // FIX: per-batch length
    if (idx == 0) g_barctr = 0u;
    // out partials: chunk0 = -out_b (so bias + sum == 0 at step 0), rest = 0
    for (int j = idx; j < 4 * Bz * DRF; j += Bz * Tz)
        g_opart[j] = (j < Bz * DRF) ? -outb[j % DRF] : 0.0f;
}

// ---------------- pm = enc @ att_enc_w^T + b, stored transposed [b][h][t] (node 2) ---
__global__ void pm_kernel(const float* __restrict__ enc,
                          const float* __restrict__ wenc,
                          const float* __restrict__ benc) {
    __shared__ float Es[16][65];
    __shared__ float Ws[16][65];
    int b  = blockIdx.z;
    int to = blockIdx.x * 64;
    int ho = blockIdx.y * 64;
    int tid = threadIdx.x;
    int tx = tid & 15, ty = tid >> 4;
    float acc[4][4];
    #pragma unroll
    for (int i = 0; i < 4; i++)
        #pragma unroll
        for (int j = 0; j < 4; j++) acc[i][j] = 0.0f;

    for (int k0 = 0; k0 < Cz; k0 += 16) {
        #pragma unroll
        for (int e = 0; e < 4; e++) {
            int i  = tid + e * 256;
            int r  = i >> 4, cc = i & 15;
            Es[cc][r] = enc[((b << 9) + to + r) * Cz + k0 + cc];
            Ws[cc][r] = wenc[(ho + r) * Cz + k0 + cc];
        }
        __syncthreads();
        #pragma unroll
        for (int cc = 0; cc < 16; cc++) {
            float ev[4], wv[4];
            #pragma unroll
            for (int i = 0; i < 4; i++) ev[i] = Es[cc][tx + 16 * i];
            #pragma unroll
            for (int j = 0; j < 4; j++) wv[j] = Ws[cc][ty + 16 * j];
            #pragma unroll
            for (int i = 0; i < 4; i++)
                #pragma unroll
                for (int j = 0; j < 4; j++) acc[i][j] += ev[i] * wv[j];
        }
        __syncthreads();
    }
    #pragma unroll
    for (int j = 0; j < 4; j++) {
        int h = ho + ty + 16 * j;
        float bb = benc[h];
        #pragma unroll
        for (int i = 0; i < 4; i++) {
            int t = to + tx + 16 * i;
            g_pm[((size_t)b * Hz + h) * Tz + t] = acc[i][j] + bb;
        }
    }
}

// ---------------- gemv tile: 64 b x 16 n, K range [kbeg,kend) --------------------
// A = A1 (rows of K1) then A2 (rows of K2) concatenated; prenetA: A = out_b + sum(partials)
__device__ void gemv_tile(float* sA, float* sW,
        const float* A1, const float* A2, int K1, int K2,
        int kbeg, int kend,
        const float* W, int ldW, const float* bias,
        int n0, int act, float* C, int ldC,
        int prenetA, const float* outb)
{
    int tid = threadIdx.x;
    int nl = tid & 15, bg = tid >> 4;        // compute roles
    int lb = tid & 63, lkq = tid >> 6;       // A loader
    int wn = tid >> 4, wkq = tid & 15;       // W loader
    float acc0 = 0.f, acc1 = 0.f, acc2 = 0.f, acc3 = 0.f;

    for (int k0 = kbeg; k0 < kend; k0 += 64) {
        int Kc = kend - k0; if (Kc > 64) Kc = 64;
        #pragma unroll
        for (int q = 0; q < 4; q++) {
            int k = lkq * 16 + q * 4;
            if (k < Kc) {
                int kg = k0 + k;
                float4 av;
                if (prenetA) {
                    float4 ob = *(const float4*)(outb + kg);
                    float4 p0 = __ldcg((const float4*)(g_opart + 0 * Bz * DRF + lb * DRF + kg));
                    float4 p1 = __ldcg((const float4*)(g_opart + 1 * Bz * DRF + lb * DRF + kg));
                    float4 p2 = __ldcg((const float4*)(g_opart + 2 * Bz * DRF + lb * DRF + kg));
                    float4 p3 = __ldcg((const float4*)(g_opart + 3 * Bz * DRF + lb * DRF + kg));
                    av.x = ob.x + p0.x + p1.x + p2.x + p3.x;
                    av.y = ob.y + p0.y + p1.y + p2.y + p3.y;
                    av.z = ob.z + p0.z + p1.z + p2.z + p3.z;
                    av.w = ob.w + p0.w + p1.w + p2.w + p3.w;
                } else if (kg < K1) {
                    av = __ldcg((const float4*)(A1 + (size_t)lb * K1 + kg));
                } else {
                    av = __ldcg((const float4*)(A2 + (size_t)lb * K2 + (kg - K1)));
                }
                sA[(k + 0) * 64 + lb] = av.x;
                sA[(k + 1) * 64 + lb] = av.y;
                sA[(k + 2) * 64 + lb] = av.z;
                sA[(k + 3) * 64 + lb] = av.w;
            }
        }
        {
            int k = wkq * 4;
            if (k < Kc) {
                float4 wv = *(const float4*)(W + (size_t)(n0 + wn) * ldW + k0 + k);
                sW[(k + 0) * 16 + wn] = wv.x;
                sW[(k + 1) * 16 + wn] = wv.y;
                sW[(k + 2) * 16 + wn] = wv.z;
                sW[(k + 3) * 16 + wn] = wv.w;
            }
        }
        __syncthreads();
        if (Kc == 64) {
            #pragma unroll 8
            for (int k = 0; k < 64; k++) {
                float w = sW[k * 16 + nl];
                const float* ap = sA + k * 64 + bg * 4;
                acc0 += ap[0] * w; acc1 += ap[1] * w;
                acc2 += ap[2] * w; acc3 += ap[3] * w;
            }
        } else {
            for (int k = 0; k < Kc; k++) {
                float w = sW[k * 16 + nl];
                const float* ap = sA + k * 64 + bg * 4;
                acc0 += ap[0] * w; acc1 += ap[1] * w;
                acc2 += ap[2] * w; acc3 += ap[3] * w;
            }
        }
        __syncthreads();
    }
    float bv = bias ? __ldg(bias + n0 + nl) : 0.0f;
    float v0 = acc0 + bv, v1 = acc1 + bv, v2 = acc2 + bv, v3 = acc3 + bv;
    if (act) {
        v0 = fmaxf(v0, 0.f); v1 = fmaxf(v1, 0.f);
        v2 = fmaxf(v2, 0.f); v3 = fmaxf(v3, 0.f);
    }
    int col = n0 + nl;
    __stcg(C + (size_t)(bg * 4 + 0) * ldC + col, v0);
    __stcg(C + (size_t)(bg * 4 + 1) * ldC + col, v1);
    __stcg(C + (size_t)(bg * 4 + 2) * ldC + col, v2);
    __stcg(C + (size_t)(bg * 4 + 3) * ldC + col, v3);
}

// ---------------- attention energy tile: (b, 256 t's), full 512 h ----------------
__device__ void erg_tile(int step, int b, int tbase,
                         const float* s_locw, const float* s_conv, const float* s_v,
                         float* s_dyn) {
    float* s_dec = s_dyn;          // 512
    float* s_pw  = s_dyn + 512;    // 286
    int tid = threadIdx.x;
    for (int i = tid; i < Hz; i += NT) s_dec[i] = __ldcg(g_dec + b * Hz + i);
    const float* prev = (step == 0) ? g_att_prev0 : g_att_sum;
    for (int i = tid; i < 256 + KW - 1; i += NT) {
        int gt = tbase + i - (KW / 2);
        s_pw[i] = (gt >= 0 && gt < Tz) ? __ldcg(prev + b * Tz + gt) : 0.0f;
    }
    __syncthreads();
    int t = tbase + tid;
    float f[CCH];
    #pragma unroll
    for (int c = 0; c < CCH; c++) {
        float a = 0.0f;
        #pragma unroll
        for (int k = 0; k < KW; k++) a += s_conv[c * KW + k] * s_pw[tid + k];
        f[c] = a;
    }
    const float* pmp = g_pm + ((size_t)b * Hz) * Tz + t;
    float acc = 0.0f;
    #pragma unroll 2
    for (int h = 0; h < Hz; h++) {
        const float4* wr = (const float4*)(s_locw + h * CCH);
        float d0 = 0.f, d1 = 0.f;
        #pragma unroll
        for (int q = 0; q < 8; q += 2) {
            float4 w0 = wr[q], w1 = wr[q + 1];
            d0 += f[4*q+0]*w0.x + f[4*q+1]*w0.y + f[4*q+2]*w0.z + f[4*q+3]*w0.w;
            d1 += f[4*q+4]*w1.x + f[4*q+5]*w1.y + f[4*q+6]*w1.z + f[4*q+7]*w1.w;
        }
        float arg = __ldg(pmp + (size_t)h * Tz) + s_dec[h] + d0 + d1;
        acc += s_v[h] * ftanh(arg);
    }
    __stcg(g_erg + b * Tz + t, acc);
    __syncthreads();
}

// ---------------- softmax + context for one b ----------------
__device__ void softctx_tile(int b, int step, float* s_dyn, const Params& p) {
    float* s_w   = s_dyn;          // 512
    float* s_red = s_dyn + 512;    // 9
    int tid = threadIdx.x;
    int len = g_len[b];
    float e0 = __ldcg(g_erg + b * Tz + tid);
    float e1 = __ldcg(g_erg + b * Tz + 256 + tid);
    if (tid >= len) e0 = -1e30f;
    if (tid + 256 >= len) e1 = -1e30f;
    float m = fmaxf(e0, e1);
    #pragma unroll
    for (int o = 16; o; o >>= 1) m = fmaxf(m, __shfl_xor_sync(0xffffffffu, m, o));
    if ((tid & 31) == 0) s_red[tid >> 5] = m;
    __syncthreads();
    if (tid == 0) {
        float mm = s_red[0];
        #pragma unroll
        for (int j = 1; j < 8; j++) mm = fmaxf(mm, s_red[j]);
        s_red[8] = mm;
    }
    __syncthreads();
    float mall = s_red[8];
    float p0 = __expf(e0 - mall), p1 = __expf(e1 - mall);
    float s = p0 + p1;
    #pragma unroll
    for (int o = 16; o; o >>= 1) s += __shfl_xor_sync(0xffffffffu, s, o);
    __syncthreads();                 // everyone has read mall
    if ((tid & 31) == 0) s_red[tid >> 5] = s;
    __syncthreads();
    if (tid == 0) {
        float ss = 0.f;
        #pragma unroll
        for (int j = 0; j < 8; j++) ss += s_red[j];
        s_red[8] = ss;
    }
    __syncthreads();
    float inv = __fdividef(1.0f, s_red[8]);
    float w0 = p0 * inv, w1 = p1 * inv;
    s_w[tid] = w0; s_w[tid + 256] = w1;
    __stcg(g_att_sum + b * Tz + tid,       __ldcg(g_att_sum + b * Tz + tid) + w0);
    __stcg(g_att_sum + b * Tz + 256 + tid, __ldcg(g_att_sum + b * Tz + 256 + tid) + w1);
    p.attw[(size_t)b * Tz * Tz + (size_t)tid * Tz + step] = w0;
    p.attw[(size_t)b * Tz * Tz + (size_t)(tid + 256) * Tz + step] = w1;
    __syncthreads();
    // context: thread handles channels (2*tid, 2*tid+1)
    const float* eb = p.enc + (size_t)b * Tz * Cz;
    float ax0 = 0.f, ay0 = 0.f, ax1 = 0.f, ay1 = 0.f;
    #pragma unroll 4
    for (int tt = 0; tt < Tz; tt += 2) {
        float wa = s_w[tt], wb = s_w[tt + 1];
        float2 ea = *(const float2*)(eb + (size_t)tt * Cz + 2 * tid);
        float2 eb2 = *(const float2*)(eb + (size_t)(tt + 1) * Cz + 2 * tid);
        ax0 += wa * ea.x;  ay0 += wa * ea.y;
        ax1 += wb * eb2.x; ay1 += wb * eb2.y;
    }
    float2 r; r.x = ax0 + ax1; r.y = ay0 + ay1;
    __stcg((float2*)(g_attc + b * Cz) + tid, r);
    __syncthreads();
}

// ---------------- GRU gate combine ----------------
__device__ void comb_phase(const float* gi, const float* gh, float* h) {
    int idx = blockIdx.x * NT + threadIdx.x;
    if (idx < Bz * Hz) {
        int b = idx >> 9, n = idx & 511;
        const float* gib = gi + (size_t)b * G3H;
        const float* ghb = gh + (size_t)b * G3H;
        float r  = fsigm(__ldcg(gib + n)        + __ldcg(ghb + n));
        float z  = fsigm(__ldcg(gib + 512 + n)  + __ldcg(ghb + 512 + n));
        float nn = ftanh(__ldcg(gib + 1024 + n) + r * __ldcg(ghb + 1024 + n));
        float hv = __ldcg(h + idx);
        __stcg(h + idx, (1.0f - z) * nn + z * hv);
    }
}

// ---------------- out finisher: write out(tstep) = bias + sum(partials) ----------
__device__ void outfin_block(int tstep, const Params& p) {
    for (int i = threadIdx.x; i < Bz * DRF; i += NT) {
        int b = i / DRF, n = i - b * DRF;
        float v = __ldg(p.out_b + n)
                + __ldcg(g_opart + i)
                + __ldcg(g_opart + Bz * DRF + i)
                + __ldcg(g_opart + 2 * Bz * DRF + i)
                + __ldcg(g_opart + 3 * Bz * DRF + i);
        p.outp[(size_t)b * 81920 + (size_t)(n >> 1) * 1024 + 2 * tstep + (n & 1)] = v;
    }
}

// ---------------- the persistent decoder (graph node 3) ----------------
__global__ __launch_bounds__(NT, 1) void decoder_kernel(Params p) {
    extern __shared__ float sm[];
    float* s_locw = sm;                       // 512*32 = 16384
    float* s_conv = sm + 16384;               // 992 (reserve 1024)
    float* s_v    = sm + 16384 + 1024;        // 512
    float* s_dyn  = s_v + 512;                // 5120
    float* sA = s_dyn;                        // 4096
    float* sW = s_dyn + 4096;                 // 1024
    int tid = threadIdx.x;
    for (int i = tid; i < Hz * CCH; i += NT) s_locw[i] = p.att_loc_w[i];
    for (int i = tid; i < CCH * KW; i += NT) s_conv[i] = p.att_conv_w[i];
    for (int i = tid; i < Hz;       i += NT) s_v[i] = p.att_v_w[i];
    __syncthreads();

    unsigned bno = 0;
    for (int t = 0; t < Tz; t++) {
        // -------- phase A: dec, gh0, gh1, x1(from partials), out(t-1) --------
        for (int w = blockIdx.x; w < 241; w += NB) {
            if (w < 32)
                gemv_tile(sA, sW, g_h0, 0, Hz, 0, 0, Hz, p.att_dec_w, Hz, 0,
                          w * 16, 0, g_dec, Hz, 0, 0);
            else if (w < 128)
                gemv_tile(sA, sW, g_h0, 0, Hz, 0, 0, Hz, p.g0_whh, Hz, p.g0_bhh,
                          (w - 32) * 16, 0, g_gh0, G3H, 0, 0);
            else if (w < 224)
                gemv_tile(sA, sW, g_h1, 0, Hz, 0, 0, Hz, p.g1_whh, Hz, p.g1_bhh,
                          (w - 128) * 16, 0, g_gh1, G3H, 0, 0);
            else if (w < 240)
                gemv_tile(sA, sW, 0, 0, 0, 0, 0, PINK, p.pn_w1, PINK, p.pn_b1,
                          (w - 224) * 16, 1, g_x1, PINNER, 1, p.out_b);
            else if (t > 0)
                outfin_block(t - 1, p);
        }
        gridbar(bno);
        // -------- phase B: attention energies + x2 --------
        for (int w = blockIdx.x; w < 160; w += NB) {
            if (w < 128)
                erg_tile(t, w >> 1, (w & 1) * 256, s_locw, s_conv, s_v, s_dyn);
            else
                gemv_tile(sA, sW, g_x1, 0, PINNER, 0, 0, PINNER, p.pn_w2, PINNER,
                          p.pn_b2, (w - 128) * 16, 1, g_x2, Hz, 0, 0);
        }
        gridbar(bno);
        // -------- phase C: softmax + context + att_sum + attw out --------
        for (int w = blockIdx.x; w < Bz; w += NB) softctx_tile(w, t, s_dyn, p);
        gridbar(bno);
        // -------- phase D: gi0 = [x2|attc] @ g0_wih^T + bih --------
        for (int w = blockIdx.x; w < 96; w += NB)
            gemv_tile(sA, sW, g_x2, g_attc, Hz, Cz, 0, Hz + Cz, p.g0_wih, Hz + Cz,
                      p.g0_bih, w * 16, 0, g_gi0, G3H, 0, 0);
        gridbar(bno);
        // -------- phase E: comb0 --------
        comb_phase(g_gi0, g_gh0, g_h0);
        gridbar(bno);
        // -------- phase F: gi1 = h0 @ g1_wih^T + bih --------
        for (int w = blockIdx.x; w < 96; w += NB)
            gemv_tile(sA, sW, g_h0, 0, Hz, 0, 0, Hz, p.g1_wih, Hz,
                      p.g1_bih, w * 16, 0, g_gi1, G3H, 0, 0);
        gridbar(bno);
        // -------- phase G: comb1 --------
        comb_phase(g_gi1, g_gh1, g_h1);
        gridbar(bno);
        // -------- phase H: out-layer partials (4 K-chunks x 10 n-tiles) --------
        for (int w = blockIdx.x; w < 40; w += NB) {
            int kc = w / 10, nt = w % 10;
            gemv_tile(sA, sW, g_h1, g_attc, Hz, Cz, kc * 256, kc * 256 + 256,
                      p.out_w, Hz + Cz, 0, nt * 16, 0,
                      g_opart + kc * Bz * DRF, DRF, 0, 0);
        }
        gridbar(bno);
    }
    // final out(t=511), grid-wide
    for (int i = blockIdx.x * NT + tid; i < Bz * DRF; i += NB * NT) {
        int b = i / DRF, n = i - b * DRF;
        float v = __ldg(p.out_b + n)
                + __ldcg(g_opart + i)
                + __ldcg(g_opart + Bz * DRF + i)
                + __ldcg(g_opart + 2 * Bz * DRF + i)
                + __ldcg(g_opart + 3 * Bz * DRF + i);
        p.outp[(size_t)b * 81920 + (size_t)(n >> 1) * 1024 + 2 * 511 + (n & 1)] = v;
    }
}

// ---------------- host ----------------
extern "C" void kernel_launch(void* const* d_in, const int* in_sizes, int n_in,
                              void* d_out, int out_size) {
    const float* enc       = (const float*)d_in[0];
    const int*   data_len  = (const int*)  d_in[1];
    Params p;
    p.enc        = enc;
    p.pn_w1      = (const float*)d_in[2];
    p.pn_b1      = (const float*)d_in[3];
    p.pn_w2      = (const float*)d_in[4];
    p.pn_b2      = (const float*)d_in[5];
    const float* att_enc_w = (const float*)d_in[6];
    const float* att_enc_b = (const float*)d_in[7];
    p.att_dec_w  = (const float*)d_in[8];
    p.att_conv_w = (const float*)d_in[9];
    p.att_loc_w  = (const float*)d_in[10];
    p.att_v_w    = (const float*)d_in[11];
    p.g0_wih     = (const float*)d_in[13];
    p.g0_whh     = (const float*)d_in[14];
    p.g0_bih     = (const float*)d_in[15];
    p.g0_bhh     = (const float*)d_in[16];
    p.g1_wih     = (const float*)d_in[17];
    p.g1_whh     = (const float*)d_in[18];
    p.g1_bih     = (const float*)d_in[19];
    p.g1_bhh     = (const float*)d_in[20];
    p.out_w      = (const float*)d_in[21];
    p.out_b      = (const float*)d_in[22];
    p.outp = (float*)d_out;                           // (B, 80, 1024)
    p.attw = (float*)d_out + (size_t)Bz * 80 * 1024;  // (B, T, T)

    const int smem_bytes = (16384 + 1024 + 512 + 5120) * 4;   // 92160
    cudaFuncSetAttribute(decoder_kernel,
                         cudaFuncAttributeMaxDynamicSharedMemorySize, smem_bytes);

    reset_kernel<<<64, 512>>>(data_len, p.out_b);
    pm_kernel<<<dim3(Tz / 64, Hz / 64, Bz), 256>>>(enc, att_enc_w, att_enc_b);
    decoder_kernel<<<NB, NT, smem_bytes>>>(p);
}

// round 9
// speedup vs baseline: 1.7369x; 1.7369x over previous
#include <cuda_runtime.h>

#define NB   148
#define NT   256
#define Bz   64
#define Tz   512
#define Cz   512
#define Hz   512
#define PINK 160
#define PINNER 256
#define CCH  32
#define KW   31
#define DRF  160
#define G3H  1536

// ---------------- scratch (static device globals; no allocation) ----------------
__device__ float g_pm[Bz * Hz * Tz];          // pm transposed: [b][h][t]
__device__ float g_h0[Bz * Hz];
__device__ float g_h1[Bz * Hz];
__device__ float g_att_sum[Bz * Tz];
__device__ float g_att_prev0[Bz * Tz];
__device__ int   g_len[Bz];
__device__ float g_dec[Bz * Hz];
__device__ float g_x1[Bz * PINNER];
__device__ float g_x2[Bz * Hz];
__device__ float g_attc[Bz * Cz];
__device__ float g_erg[Bz * Tz];
__device__ float g_gi0[Bz * G3H];
__device__ float g_gi0b[Bz * G3H];
__device__ float g_gh0[Bz * G3H];
__device__ float g_gi1[Bz * G3H];
__device__ float g_gh1[Bz * G3H];
__device__ float g_opart[4 * Bz * DRF];       // out-layer K-chunk partial sums
__device__ unsigned g_barctr;

struct Params {
    const float *enc;
    const float *pn_w1, *pn_b1, *pn_w2, *pn_b2;
    const float *att_dec_w, *att_conv_w, *att_loc_w, *att_v_w;
    const float *g0_wih, *g0_whh, *g0_bih, *g0_bhh;
    const float *g1_wih, *g1_whh, *g1_bih, *g1_bhh;
    const float *out_w, *out_b;
    float *outp, *attw;
};

// ---------------- math helpers ----------------
__device__ __forceinline__ float ftanh(float x) {        // precise (GRU path)
    float ax = fabsf(x);
    float e  = __expf(-2.0f * ax);
    float r  = __fdividef(1.0f - e, 1.0f + e);
    return copysignf(r, x);
}
__device__ __forceinline__ float fsigm(float x) {
    return __fdividef(1.0f, 1.0f + __expf(-x));
}
__device__ __forceinline__ float qtanh(float x) {        // fast (attention energy only)
    float r;
    asm("tanh.approx.f32 %0, %1;" : "=f"(r) : "f"(x));
    return r;
}

// ---------------- software grid barrier (all NB blocks co-resident) ----------------
__device__ __forceinline__ void gridbar(unsigned& bno) {
    __threadfence();
    __syncthreads();
    bno++;
    if (threadIdx.x == 0) {
        atomicAdd(&g_barctr, 1u);
        unsigned target = bno * NB;
        volatile unsigned* ctr = &g_barctr;
        while (*ctr < target) __nanosleep(64);
    }
    __syncthreads();
}

// ---------------- reset (graph node 1) ----------------
__global__ void reset_kernel(const int* __restrict__ dl, const float* __restrict__ outb) {
    int idx = blockIdx.x * blockDim.x + threadIdx.x;   // 64*512 = 32768
    int b = idx >> 9, t = idx & 511;
    int len = dl[b] >> 1;
    g_att_sum[idx]   = 0.0f;
    g_att_prev0[idx] = (t < len) ? (1.0f / (float)len) : 0.0f;
    g_h0[idx] = 0.0f;
    g_h1[idx] = 0.0f;
    if (idx < Bz) g_len[idx] = dl[idx] >> 1;
    if (idx == 0) g_barctr = 0u;
    for (int j = idx; j < 4 * Bz * DRF; j += Bz * Tz)
        g_opart[j] = (j < Bz * DRF) ? -outb[j % DRF] : 0.0f;
}

// ---------------- pm = enc @ att_enc_w^T + b, stored transposed [b][h][t] (node 2) ---
__global__ void pm_kernel(const float* __restrict__ enc,
                          const float* __restrict__ wenc,
                          const float* __restrict__ benc) {
    __shared__ float Es[16][65];
    __shared__ float Ws[16][65];
    int b  = blockIdx.z;
    int to = blockIdx.x * 64;
    int ho = blockIdx.y * 64;
    int tid = threadIdx.x;
    int tx = tid & 15, ty = tid >> 4;
    float acc[4][4];
    #pragma unroll
    for (int i = 0; i < 4; i++)
        #pragma unroll
        for (int j = 0; j < 4; j++) acc[i][j] = 0.0f;

    for (int k0 = 0; k0 < Cz; k0 += 16) {
        #pragma unroll
        for (int e = 0; e < 4; e++) {
            int i  = tid + e * 256;
            int r  = i >> 4, cc = i & 15;
            Es[cc][r] = enc[((b << 9) + to + r) * Cz + k0 + cc];
            Ws[cc][r] = wenc[(ho + r) * Cz + k0 + cc];
        }
        __syncthreads();
        #pragma unroll
        for (int cc = 0; cc < 16; cc++) {
            float ev[4], wv[4];
            #pragma unroll
            for (int i = 0; i < 4; i++) ev[i] = Es[cc][tx + 16 * i];
            #pragma unroll
            for (int j = 0; j < 4; j++) wv[j] = Ws[cc][ty + 16 * j];
            #pragma unroll
            for (int i = 0; i < 4; i++)
                #pragma unroll
                for (int j = 0; j < 4; j++) acc[i][j] += ev[i] * wv[j];
        }
        __syncthreads();
    }
    #pragma unroll
    for (int j = 0; j < 4; j++) {
        int h = ho + ty + 16 * j;
        float bb = benc[h];
        #pragma unroll
        for (int i = 0; i < 4; i++) {
            int t = to + tx + 16 * i;
            g_pm[((size_t)b * Hz + h) * Tz + t] = acc[i][j] + bb;
        }
    }
}

// ---------------- fetch helpers for gemv32 ----------------
__device__ __forceinline__ void fetchA32(float4* rA, const float* A, int ldA, int akoff,
                                         int Klen, int kc0, int lb, int lkq,
                                         int prenetA, const float* outb) {
    #pragma unroll
    for (int q = 0; q < 4; q++) {
        int k = kc0 + lkq * 16 + q * 4;
        if (k < Klen) {
            if (prenetA) {
                float4 ob = *(const float4*)(outb + k);
                float4 p0 = __ldcg((const float4*)(g_opart + 0 * Bz * DRF + lb * DRF + k));
                float4 p1 = __ldcg((const float4*)(g_opart + 1 * Bz * DRF + lb * DRF + k));
                float4 p2 = __ldcg((const float4*)(g_opart + 2 * Bz * DRF + lb * DRF + k));
                float4 p3 = __ldcg((const float4*)(g_opart + 3 * Bz * DRF + lb * DRF + k));
                rA[q].x = ob.x + p0.x + p1.x + p2.x + p3.x;
                rA[q].y = ob.y + p0.y + p1.y + p2.y + p3.y;
                rA[q].z = ob.z + p0.z + p1.z + p2.z + p3.z;
                rA[q].w = ob.w + p0.w + p1.w + p2.w + p3.w;
            } else {
                rA[q] = __ldcg((const float4*)(A + (size_t)lb * ldA + akoff + k));
            }
        }
    }
}
__device__ __forceinline__ void fetchW32(float4* rW, const float* W, int ldW, int wkoff,
                                         int Klen, int kc0, int n0, int wn, int wk8) {
    int k = kc0 + wk8 * 8;
    const float* wr = W + (size_t)(n0 + wn) * ldW + wkoff;
    if (k < Klen)     rW[0] = *(const float4*)(wr + k);
    if (k + 4 < Klen) rW[1] = *(const float4*)(wr + k + 4);
}

// ---------------- gemv32: C[64b x 32n] = act(A[64 x Klen] @ W[n, Klen]^T + bias) ------
__device__ void gemv32(float* sA, float* sW,
        const float* A, int ldA, int akoff, int Klen,
        const float* W, int ldW, int wkoff,
        const float* bias, int n0, int act,
        float* C, int ldC,
        int prenetA, const float* outb)
{
    int tid = threadIdx.x;
    int nl = tid & 31, bg = tid >> 5;        // compute: 32 n lanes, 8 b-groups of 8
    int lb = tid & 63, lkq = tid >> 6;       // A loader
    int wn = tid & 31, wk8 = tid >> 5;       // W loader
    float acc[8];
    #pragma unroll
    for (int i = 0; i < 8; i++) acc[i] = 0.f;

    float4 rA[4], rW[2];
    fetchA32(rA, A, ldA, akoff, Klen, 0, lb, lkq, prenetA, outb);
    fetchW32(rW, W, ldW, wkoff, Klen, 0, n0, wn, wk8);

    for (int k0 = 0; k0 < Klen; k0 += 64) {
        int Kc = Klen - k0; if (Kc > 64) Kc = 64;
        __syncthreads();                     // prior compute done before overwrite
        #pragma unroll
        for (int q = 0; q < 4; q++) {
            int k = lkq * 16 + q * 4;
            if (k < Kc) {
                sA[(k + 0) * 64 + lb] = rA[q].x;
                sA[(k + 1) * 64 + lb] = rA[q].y;
                sA[(k + 2) * 64 + lb] = rA[q].z;
                sA[(k + 3) * 64 + lb] = rA[q].w;
            }
        }
        {
            int k = wk8 * 8;
            if (k < Kc) {
                sW[(k + 0) * 32 + wn] = rW[0].x;
                sW[(k + 1) * 32 + wn] = rW[0].y;
                sW[(k + 2) * 32 + wn] = rW[0].z;
                sW[(k + 3) * 32 + wn] = rW[0].w;
            }
            if (k + 4 < Kc) {
                sW[(k + 4) * 32 + wn] = rW[1].x;
                sW[(k + 5) * 32 + wn] = rW[1].y;
                sW[(k + 6) * 32 + wn] = rW[1].z;
                sW[(k + 7) * 32 + wn] = rW[1].w;
            }
        }
        __syncthreads();
        if (k0 + 64 < Klen) {                // prefetch next chunk during compute
            fetchA32(rA, A, ldA, akoff, Klen, k0 + 64, lb, lkq, prenetA, outb);
            fetchW32(rW, W, ldW, wkoff, Klen, k0 + 64, n0, wn, wk8);
        }
        if (Kc == 64) {
            #pragma unroll 4
            for (int k = 0; k < 64; k++) {
                float w = sW[k * 32 + nl];
                const float4* ap = (const float4*)(sA + k * 64 + bg * 8);
                float4 a0 = ap[0], a1 = ap[1];
                acc[0] += a0.x * w; acc[1] += a0.y * w;
                acc[2] += a0.z * w; acc[3] += a0.w * w;
                acc[4] += a1.x * w; acc[5] += a1.y * w;
                acc[6] += a1.z * w; acc[7] += a1.w * w;
            }
        } else {
            for (int k = 0; k < Kc; k++) {
                float w = sW[k * 32 + nl];
                const float4* ap = (const float4*)(sA + k * 64 + bg * 8);
                float4 a0 = ap[0], a1 = ap[1];
                acc[0] += a0.x * w; acc[1] += a0.y * w;
                acc[2] += a0.z * w; acc[3] += a0.w * w;
                acc[4] += a1.x * w; acc[5] += a1.y * w;
                acc[6] += a1.z * w; acc[7] += a1.w * w;
            }
        }
    }
    float bv = bias ? __ldg(bias + n0 + nl) : 0.0f;
    int col = n0 + nl;
    #pragma unroll
    for (int i = 0; i < 8; i++) {
        float v = acc[i] + bv;
        if (act) v = fmaxf(v, 0.f);
        __stcg(C + (size_t)(bg * 8 + i) * ldC + col, v);
    }
}

// ---------------- attention energy tile: (b, 256 t's), full 512 h ----------------
__device__ void erg_tile(int step, int b, int tbase,
                         const float* s_locw, const float* s_conv, const float* s_v,
                         float* s_dyn) {
    float* s_dec = s_dyn;          // 512
    float* s_pw  = s_dyn + 512;    // 286
    int tid = threadIdx.x;
    for (int i = tid; i < Hz; i += NT) s_dec[i] = __ldcg(g_dec + b * Hz + i);
    const float* prev = (step == 0) ? g_att_prev0 : g_att_sum;
    for (int i = tid; i < 256 + KW - 1; i += NT) {
        int gt = tbase + i - (KW / 2);
        s_pw[i] = (gt >= 0 && gt < Tz) ? __ldcg(prev + b * Tz + gt) : 0.0f;
    }
    __syncthreads();
    int t = tbase + tid;
    float f[CCH];
    #pragma unroll
    for (int c = 0; c < CCH; c++) {
        float a = 0.0f;
        #pragma unroll
        for (int k = 0; k < KW; k++) a += s_conv[c * KW + k] * s_pw[tid + k];
        f[c] = a;
    }
    const float* pmp = g_pm + (size_t)b * Hz * Tz + t;
    float acc = 0.0f;
    float pmb[8];
    #pragma unroll
    for (int j = 0; j < 8; j++) pmb[j] = __ldcs(pmp + (size_t)j * Tz);
    for (int h0 = 0; h0 < Hz; h0 += 8) {
        float cur[8];
        #pragma unroll
        for (int j = 0; j < 8; j++) cur[j] = pmb[j];
        if (h0 + 8 < Hz) {
            const float* np = pmp + (size_t)(h0 + 8) * Tz;
            #pragma unroll
            for (int j = 0; j < 8; j++) pmb[j] = __ldcs(np + (size_t)j * Tz);
        }
        #pragma unroll
        for (int j = 0; j < 8; j++) {
            int h = h0 + j;
            const float4* wr = (const float4*)(s_locw + h * CCH);
            float d0 = 0.f, d1 = 0.f;
            #pragma unroll
            for (int q = 0; q < 8; q += 2) {
                float4 w0 = wr[q], w1 = wr[q + 1];
                d0 += f[4*q+0]*w0.x + f[4*q+1]*w0.y + f[4*q+2]*w0.z + f[4*q+3]*w0.w;
                d1 += f[4*q+4]*w1.x + f[4*q+5]*w1.y + f[4*q+6]*w1.z + f[4*q+7]*w1.w;
            }
            float arg = cur[j] + s_dec[h] + d0 + d1;
            acc += s_v[h] * qtanh(arg);
        }
    }
    __stcg(g_erg + b * Tz + t, acc);
    __syncthreads();
}

// ---------------- softmax + half the context for one b ----------------
__device__ void softctx_half(int b, int half, int step, float* s_dyn, const Params& p) {
    float* s_w   = s_dyn;          // 512
    float* s_red = s_dyn + 512;    // 9
    int tid = threadIdx.x;
    int len = g_len[b];
    float e0 = __ldcg(g_erg + b * Tz + tid);
    float e1 = __ldcg(g_erg + b * Tz + 256 + tid);
    if (tid >= len) e0 = -1e30f;
    if (tid + 256 >= len) e1 = -1e30f;
    float m = fmaxf(e0, e1);
    #pragma unroll
    for (int o = 16; o; o >>= 1) m = fmaxf(m, __shfl_xor_sync(0xffffffffu, m, o));
    if ((tid & 31) == 0) s_red[tid >> 5] = m;
    __syncthreads();
    if (tid == 0) {
        float mm = s_red[0];
        #pragma unroll
        for (int j = 1; j < 8; j++) mm = fmaxf(mm, s_red[j]);
        s_red[8] = mm;
    }
    __syncthreads();
    float mall = s_red[8];
    float p0 = __expf(e0 - mall), p1 = __expf(e1 - mall);
    float s = p0 + p1;
    #pragma unroll
    for (int o = 16; o; o >>= 1) s += __shfl_xor_sync(0xffffffffu, s, o);
    __syncthreads();
    if ((tid & 31) == 0) s_red[tid >> 5] = s;
    __syncthreads();
    if (tid == 0) {
        float ss = 0.f;
        #pragma unroll
        for (int j = 0; j < 8; j++) ss += s_red[j];
        s_red[8] = ss;
    }
    __syncthreads();
    float inv = __fdividef(1.0f, s_red[8]);
    float w0 = p0 * inv, w1 = p1 * inv;
    s_w[tid] = w0; s_w[tid + 256] = w1;
    // this half-block owns t range [half*256, half*256+256) for global updates
    int tg = half * 256 + tid;
    float wmine = half ? w1 : w0;
    __stcg(g_att_sum + b * Tz + tg, __ldcg(g_att_sum + b * Tz + tg) + wmine);
    p.attw[(size_t)b * Tz * Tz + (size_t)tg * Tz + step] = wmine;
    __syncthreads();
    // context: this half-block owns channels [half*256, half*256+256), 1 per thread
    int c = half * 256 + tid;
    const float* eb = p.enc + (size_t)b * Tz * Cz + c;
    float a0 = 0.f, a1 = 0.f, a2 = 0.f, a3 = 0.f;
    for (int tt = 0; tt < Tz; tt += 4) {
        a0 += s_w[tt + 0] * __ldcs(eb + (size_t)(tt + 0) * Cz);
        a1 += s_w[tt + 1] * __ldcs(eb + (size_t)(tt + 1) * Cz);
        a2 += s_w[tt + 2] * __ldcs(eb + (size_t)(tt + 2) * Cz);
        a3 += s_w[tt + 3] * __ldcs(eb + (size_t)(tt + 3) * Cz);
    }
    __stcg(g_attc + b * Cz + c, (a0 + a1) + (a2 + a3));
    __syncthreads();
}

// ---------------- GRU gate combine (gi2 optional second partial) ----------------
__device__ void comb_phase(const float* gi, const float* gi2, const float* gh, float* h) {
    int idx = blockIdx.x * NT + threadIdx.x;
    if (idx < Bz * Hz) {
        int b = idx >> 9, n = idx & 511;
        const float* gib = gi + (size_t)b * G3H;
        const float* ghb = gh + (size_t)b * G3H;
        float i0 = __ldcg(gib + n), i1 = __ldcg(gib + 512 + n), i2 = __ldcg(gib + 1024 + n);
        if (gi2) {
            const float* g2 = gi2 + (size_t)b * G3H;
            i0 += __ldcg(g2 + n); i1 += __ldcg(g2 + 512 + n); i2 += __ldcg(g2 + 1024 + n);
        }
        float r  = fsigm(i0 + __ldcg(ghb + n));
        float z  = fsigm(i1 + __ldcg(ghb + 512 + n));
        float nn = ftanh(i2 + r * __ldcg(ghb + 1024 + n));
        float hv = __ldcg(h + idx);
        __stcg(h + idx, (1.0f - z) * nn + z * hv);
    }
}

// ---------------- out finisher: write out(tstep) = bias + sum(partials) ----------
__device__ void outfin_block(int tstep, const Params& p) {
    for (int i = threadIdx.x; i < Bz * DRF; i += NT) {
        int b = i / DRF, n = i - b * DRF;
        float v = __ldg(p.out_b + n)
                + __ldcg(g_opart + i)
                + __ldcg(g_opart + Bz * DRF + i)
                + __ldcg(g_opart + 2 * Bz * DRF + i)
                + __ldcg(g_opart + 3 * Bz * DRF + i);
        p.outp[(size_t)b * 81920 + (size_t)(n >> 1) * 1024 + 2 * tstep + (n & 1)] = v;
    }
}

// ---------------- the persistent decoder (graph node 3) ----------------
__global__ __launch_bounds__(NT, 1) void decoder_kernel(Params p) {
    extern __shared__ float sm[];
    float* s_locw = sm;                       // 16384
    float* s_conv = sm + 16384;               // 1024 (992 used)
    float* s_v    = sm + 16384 + 1024;        // 512
    float* s_dyn  = s_v + 512;                // 6144
    float* sA = s_dyn;                        // 4096
    float* sW = s_dyn + 4096;                 // 2048
    int tid = threadIdx.x;
    for (int i = tid; i < Hz * CCH; i += NT) s_locw[i] = p.att_loc_w[i];
    for (int i = tid; i < CCH * KW; i += NT) s_conv[i] = p.att_conv_w[i];
    for (int i = tid; i < Hz;       i += NT) s_v[i] = p.att_v_w[i];
    __syncthreads();

    unsigned bno = 0;
    for (int t = 0; t < Tz; t++) {
        // ---- phase A: dec(16) gh0(48) gh1(48) x1(8) outfin(1) = 121 units ----
        for (int w = blockIdx.x; w < 121; w += NB) {
            if (w < 16)
                gemv32(sA, sW, g_h0, Hz, 0, Hz, p.att_dec_w, Hz, 0,
                       0, w * 32, 0, g_dec, Hz, 0, 0);
            else if (w < 64)
                gemv32(sA, sW, g_h0, Hz, 0, Hz, p.g0_whh, Hz, 0,
                       p.g0_bhh, (w - 16) * 32, 0, g_gh0, G3H, 0, 0);
            else if (w < 112)
                gemv32(sA, sW, g_h1, Hz, 0, Hz, p.g1_whh, Hz, 0,
                       p.g1_bhh, (w - 64) * 32, 0, g_gh1, G3H, 0, 0);
            else if (w < 120)
                gemv32(sA, sW, 0, 0, 0, PINK, p.pn_w1, PINK, 0,
                       p.pn_b1, (w - 112) * 32, 1, g_x1, PINNER, 1, p.out_b);
            else if (t > 0)
                outfin_block(t - 1, p);
        }
        gridbar(bno);
        // ---- phase B: attention energies, 1 tile per block ----
        for (int w = blockIdx.x; w < 128; w += NB)
            erg_tile(t, w >> 1, (w & 1) * 256, s_locw, s_conv, s_v, s_dyn);
        gridbar(bno);
        // ---- phase C: softmax/context halves (128) + x2 (16) = 144 units ----
        for (int w = blockIdx.x; w < 144; w += NB) {
            if (w < 128)
                softctx_half(w >> 1, w & 1, t, s_dyn, p);
            else
                gemv32(sA, sW, g_x1, PINNER, 0, PINNER, p.pn_w2, PINNER, 0,
                       p.pn_b2, (w - 128) * 32, 1, g_x2, Hz, 0, 0);
        }
        gridbar(bno);
        // ---- phase D: gi0 partials (x2 part 48, attc part 48) ----
        for (int w = blockIdx.x; w < 96; w += NB) {
            if (w < 48)
                gemv32(sA, sW, g_x2, Hz, 0, Hz, p.g0_wih, Hz + Cz, 0,
                       p.g0_bih, w * 32, 0, g_gi0, G3H, 0, 0);
            else
                gemv32(sA, sW, g_attc, Cz, 0, Cz, p.g0_wih, Hz + Cz, Hz,
                       0, (w - 48) * 32, 0, g_gi0b, G3H, 0, 0);
        }
        gridbar(bno);
        // ---- phase E: comb0 ----
        comb_phase(g_gi0, g_gi0b, g_gh0, g_h0);
        gridbar(bno);
        // ---- phase F: gi1 (48) ----
        for (int w = blockIdx.x; w < 48; w += NB)
            gemv32(sA, sW, g_h0, Hz, 0, Hz, p.g1_wih, Hz, 0,
                   p.g1_bih, w * 32, 0, g_gi1, G3H, 0, 0);
        gridbar(bno);
        // ---- phase G: comb1 ----
        comb_phase(g_gi1, 0, g_gh1, g_h1);
        gridbar(bno);
        // ---- phase H: out partials (4 kc x 5 ntiles = 20) ----
        for (int w = blockIdx.x; w < 20; w += NB) {
            int kc = w / 5, nt = w % 5;
            const float* A = (kc < 2) ? g_h1 : g_attc;
            int akoff = (kc & 1) * 256;
            gemv32(sA, sW, A, Hz, akoff, 256, p.out_w, Hz + Cz, kc * 256,
                   0, nt * 32, 0, g_opart + kc * Bz * DRF, DRF, 0, 0);
        }
        gridbar(bno);
    }
    // final out(t=511), grid-wide
    for (int i = blockIdx.x * NT + tid; i < Bz * DRF; i += NB * NT) {
        int b = i / DRF, n = i - b * DRF;
        float v = __ldg(p.out_b + n)
                + __ldcg(g_opart + i)
                + __ldcg(g_opart + Bz * DRF + i)
                + __ldcg(g_opart + 2 * Bz * DRF + i)
                + __ldcg(g_opart + 3 * Bz * DRF + i);
        p.outp[(size_t)b * 81920 + (size_t)(n >> 1) * 1024 + 2 * 511 + (n & 1)] = v;
    }
}

// ---------------- host ----------------
extern "C" void kernel_launch(void* const* d_in, const int* in_sizes, int n_in,
                              void* d_out, int out_size) {
    const float* enc       = (const float*)d_in[0];
    const int*   data_len  = (const int*)  d_in[1];
    Params p;
    p.enc        = enc;
    p.pn_w1      = (const float*)d_in[2];
    p.pn_b1      = (const float*)d_in[3];
    p.pn_w2      = (const float*)d_in[4];
    p.pn_b2      = (const float*)d_in[5];
    const float* att_enc_w = (const float*)d_in[6];
    const float* att_enc_b = (const float*)d_in[7];
    p.att_dec_w  = (const float*)d_in[8];
    p.att_conv_w = (const float*)d_in[9];
    p.att_loc_w  = (const float*)d_in[10];
    p.att_v_w    = (const float*)d_in[11];
    p.g0_wih     = (const float*)d_in[13];
    p.g0_whh     = (const float*)d_in[14];
    p.g0_bih     = (const float*)d_in[15];
    p.g0_bhh     = (const float*)d_in[16];
    p.g1_wih     = (const float*)d_in[17];
    p.g1_whh     = (const float*)d_in[18];
    p.g1_bih     = (const float*)d_in[19];
    p.g1_bhh     = (const float*)d_in[20];
    p.out_w      = (const float*)d_in[21];
    p.out_b      = (const float*)d_in[22];
    p.outp = (float*)d_out;                           // (B, 80, 1024)
    p.attw = (float*)d_out + (size_t)Bz * 80 * 1024;  // (B, T, T)

    const int smem_bytes = (16384 + 1024 + 512 + 6144) * 4;   // 96256
    cudaFuncSetAttribute(decoder_kernel,
                         cudaFuncAttributeMaxDynamicSharedMemorySize, smem_bytes);

    reset_kernel<<<64, 512>>>(data_len, p.out_b);
    pm_kernel<<<dim3(Tz / 64, Hz / 64, Bz), 256>>>(enc, att_enc_w, att_enc_b);
    decoder_kernel<<<NB, NT, smem_bytes>>>(p);
}

// round 11
// speedup vs baseline: 2.6389x; 1.5193x over previous
#include <cuda_runtime.h>
#include <cuda_fp16.h>

#define NB   148
#define NT   256
#define Bz   64
#define Tz   512
#define Cz   512
#define Hz   512
#define PINK 160
#define PINNER 256
#define CCH  32
#define KW   31
#define DRF  160
#define G3H  1536

// ---------------- scratch (static device globals; no allocation) ----------------
__device__ float g_pm[Bz * Hz * Tz];          // pm transposed: [b][h][t]
__device__ float g_h0[Bz * Hz];
__device__ float g_h1[Bz * Hz];
__device__ float g_att_sum[Bz * Tz];
__device__ float g_att_prev0[Bz * Tz];
__device__ int   g_len[Bz];
__device__ float g_dec[Bz * Hz];
__device__ float g_x1[Bz * PINNER];
__device__ float g_x2[Bz * Hz];
__device__ float g_attc[Bz * Cz];
__device__ float g_erg[Bz * Tz];
__device__ float g_gi0[Bz * G3H];
__device__ float g_gi0b[Bz * G3H];
__device__ float g_gh0[Bz * G3H];
__device__ float g_gi1[Bz * G3H];
__device__ float g_gi1b[Bz * G3H];
__device__ float g_gh1[Bz * G3H];
__device__ float g_opart[4 * Bz * DRF];       // out-layer K-chunk partial sums
__device__ unsigned g_barctr;

struct Params {
    const float *enc;
    const float *pn_w1, *pn_b1, *pn_w2, *pn_b2;
    const float *att_dec_w, *att_conv_w, *att_loc_w, *att_v_w;
    const float *g0_wih, *g0_whh, *g0_bih, *g0_bhh;
    const float *g1_wih, *g1_whh, *g1_bih, *g1_bhh;
    const float *out_w, *out_b;
    float *outp, *attw;
};

// ---------------- math helpers ----------------
__device__ __forceinline__ float ftanh(float x) {        // precise (GRU path)
    float ax = fabsf(x);
    float e  = __expf(-2.0f * ax);
    float r  = __fdividef(1.0f - e, 1.0f + e);
    return copysignf(r, x);
}
__device__ __forceinline__ float fsigm(float x) {
    return __fdividef(1.0f, 1.0f + __expf(-x));
}
__device__ __forceinline__ float qtanh(float x) {        // fast (attention energy only)
    float r;
    asm("tanh.approx.f32 %0, %1;" : "=f"(r) : "f"(x));
    return r;
}

// ---------------- software grid barrier (all NB blocks co-resident) ----------------
__device__ __forceinline__ void gridbar(unsigned& bno) {
    __threadfence();
    __syncthreads();
    bno++;
    if (threadIdx.x == 0) {
        atomicAdd(&g_barctr, 1u);
        unsigned target = bno * NB;
        volatile unsigned* ctr = &g_barctr;
        while (*ctr < target) __nanosleep(64);
    }
    __syncthreads();
}

// ---------------- reset (graph node 1) ----------------
__global__ void reset_kernel(const int* __restrict__ dl, const float* __restrict__ outb,
                             const float* __restrict__ bhh0, const float* __restrict__ bhh1) {
    int idx = blockIdx.x * blockDim.x + threadIdx.x;   // 64*512 = 32768
    int b = idx >> 9, t = idx & 511;
    int len = dl[b] >> 1;
    g_att_sum[idx]   = 0.0f;
    g_att_prev0[idx] = (t < len) ? (1.0f / (float)len) : 0.0f;
    g_h0[idx] = 0.0f;
    g_h1[idx] = 0.0f;
    g_dec[idx] = 0.0f;
    if (idx < Bz) g_len[idx] = dl[idx] >> 1;
    if (idx == 0) g_barctr = 0u;
    for (int j = idx; j < 4 * Bz * DRF; j += Bz * Tz)
        g_opart[j] = (j < Bz * DRF) ? -outb[j % DRF] : 0.0f;
    for (int j = idx; j < Bz * G3H; j += Bz * Tz) {     // gh seeded with bhh (t=0: h=0)
        int n = j % G3H;
        g_gh0[j] = bhh0[n];
        g_gh1[j] = bhh1[n];
    }
}

// ---------------- pm = enc @ att_enc_w^T + b, stored transposed [b][h][t] (node 2) ---
__global__ void pm_kernel(const float* __restrict__ enc,
                          const float* __restrict__ wenc,
                          const float* __restrict__ benc) {
    __shared__ float Es[16][65];
    __shared__ float Ws[16][65];
    int b  = blockIdx.z;
    int to = blockIdx.x * 64;
    int ho = blockIdx.y * 64;
    int tid = threadIdx.x;
    int tx = tid & 15, ty = tid >> 4;
    float acc[4][4];
    #pragma unroll
    for (int i = 0; i < 4; i++)
        #pragma unroll
        for (int j = 0; j < 4; j++) acc[i][j] = 0.0f;

    for (int k0 = 0; k0 < Cz; k0 += 16) {
        #pragma unroll
        for (int e = 0; e < 4; e++) {
            int i  = tid + e * 256;
            int r  = i >> 4, cc = i & 15;
            Es[cc][r] = enc[((b << 9) + to + r) * Cz + k0 + cc];
            Ws[cc][r] = wenc[(ho + r) * Cz + k0 + cc];
        }
        __syncthreads();
        #pragma unroll
        for (int cc = 0; cc < 16; cc++) {
            float ev[4], wv[4];
            #pragma unroll
            for (int i = 0; i < 4; i++) ev[i] = Es[cc][tx + 16 * i];
            #pragma unroll
            for (int j = 0; j < 4; j++) wv[j] = Ws[cc][ty + 16 * j];
            #pragma unroll
            for (int i = 0; i < 4; i++)
                #pragma unroll
                for (int j = 0; j < 4; j++) acc[i][j] += ev[i] * wv[j];
        }
        __syncthreads();
    }
    #pragma unroll
    for (int j = 0; j < 4; j++) {
        int h = ho + ty + 16 * j;
        float bb = benc[h];
        #pragma unroll
        for (int i = 0; i < 4; i++) {
            int t = to + tx + 16 * i;
            g_pm[((size_t)b * Hz + h) * Tz + t] = acc[i][j] + bb;
        }
    }
}

// ---------------- fetch helpers for gemv32 ----------------
__device__ __forceinline__ void fetchA32(float4* rA, const float* A, int ldA, int akoff,
                                         int Klen, int kc0, int lb, int lkq,
                                         int prenetA, const float* outb) {
    #pragma unroll
    for (int q = 0; q < 4; q++) {
        int k = kc0 + lkq * 16 + q * 4;
        if (k < Klen) {
            if (prenetA) {
                float4 ob = *(const float4*)(outb + k);
                float4 p0 = __ldcg((const float4*)(g_opart + 0 * Bz * DRF + lb * DRF + k));
                float4 p1 = __ldcg((const float4*)(g_opart + 1 * Bz * DRF + lb * DRF + k));
                float4 p2 = __ldcg((const float4*)(g_opart + 2 * Bz * DRF + lb * DRF + k));
                float4 p3 = __ldcg((const float4*)(g_opart + 3 * Bz * DRF + lb * DRF + k));
                rA[q].x = ob.x + p0.x + p1.x + p2.x + p3.x;
                rA[q].y = ob.y + p0.y + p1.y + p2.y + p3.y;
                rA[q].z = ob.z + p0.z + p1.z + p2.z + p3.z;
                rA[q].w = ob.w + p0.w + p1.w + p2.w + p3.w;
            } else {
                rA[q] = __ldcg((const float4*)(A + (size_t)lb * ldA + akoff + k));
            }
        }
    }
}
__device__ __forceinline__ void fetchW32(float4* rW, const float* W, int ldW, int wkoff,
                                         int Klen, int kc0, int n0, int wn, int wk8) {
    int k = kc0 + wk8 * 8;
    const float* wr = W + (size_t)(n0 + wn) * ldW + wkoff;
    if (k < Klen)     rW[0] = *(const float4*)(wr + k);
    if (k + 4 < Klen) rW[1] = *(const float4*)(wr + k + 4);
}

// ---------------- gemv32: C[64b x 32n] = act(A[64 x Klen] @ W[n, Klen]^T + bias) ------
__device__ void gemv32(float* sA, float* sW,
        const float* A, int ldA, int akoff, int Klen,
        const float* W, int ldW, int wkoff,
        const float* bias, int n0, int act,
        float* C, int ldC,
        int prenetA, const float* outb)
{
    int tid = threadIdx.x;
    int nl = tid & 31, bg = tid >> 5;        // compute: 32 n lanes, 8 b-groups of 8
    int lb = tid & 63, lkq = tid >> 6;       // A loader
    int wn = tid & 31, wk8 = tid >> 5;       // W loader
    float acc[8];
    #pragma unroll
    for (int i = 0; i < 8; i++) acc[i] = 0.f;

    float4 rA[4], rW[2];
    fetchA32(rA, A, ldA, akoff, Klen, 0, lb, lkq, prenetA, outb);
    fetchW32(rW, W, ldW, wkoff, Klen, 0, n0, wn, wk8);

    for (int k0 = 0; k0 < Klen; k0 += 64) {
        int Kc = Klen - k0; if (Kc > 64) Kc = 64;
        __syncthreads();                     // prior compute done before overwrite
        #pragma unroll
        for (int q = 0; q < 4; q++) {
            int k = lkq * 16 + q * 4;
            if (k < Kc) {
                sA[(k + 0) * 64 + lb] = rA[q].x;
                sA[(k + 1) * 64 + lb] = rA[q].y;
                sA[(k + 2) * 64 + lb] = rA[q].z;
                sA[(k + 3) * 64 + lb] = rA[q].w;
            }
        }
        {
            int k = wk8 * 8;
            if (k < Kc) {
                sW[(k + 0) * 32 + wn] = rW[0].x;
                sW[(k + 1) * 32 + wn] = rW[0].y;
                sW[(k + 2) * 32 + wn] = rW[0].z;
                sW[(k + 3) * 32 + wn] = rW[0].w;
            }
            if (k + 4 < Kc) {
                sW[(k + 4) * 32 + wn] = rW[1].x;
                sW[(k + 5) * 32 + wn] = rW[1].y;
                sW[(k + 6) * 32 + wn] = rW[1].z;
                sW[(k + 7) * 32 + wn] = rW[1].w;
            }
        }
        __syncthreads();
        if (k0 + 64 < Klen) {                // prefetch next chunk during compute
            fetchA32(rA, A, ldA, akoff, Klen, k0 + 64, lb, lkq, prenetA, outb);
            fetchW32(rW, W, ldW, wkoff, Klen, k0 + 64, n0, wn, wk8);
        }
        if (Kc == 64) {
            #pragma unroll 4
            for (int k = 0; k < 64; k++) {
                float w = sW[k * 32 + nl];
                const float4* ap = (const float4*)(sA + k * 64 + bg * 8);
                float4 a0 = ap[0], a1 = ap[1];
                acc[0] += a0.x * w; acc[1] += a0.y * w;
                acc[2] += a0.z * w; acc[3] += a0.w * w;
                acc[4] += a1.x * w; acc[5] += a1.y * w;
                acc[6] += a1.z * w; acc[7] += a1.w * w;
            }
        } else {
            for (int k = 0; k < Kc; k++) {
                float w = sW[k * 32 + nl];
                const float4* ap = (const float4*)(sA + k * 64 + bg * 8);
                float4 a0 = ap[0], a1 = ap[1];
                acc[0] += a0.x * w; acc[1] += a0.y * w;
                acc[2] += a0.z * w; acc[3] += a0.w * w;
                acc[4] += a1.x * w; acc[5] += a1.y * w;
                acc[6] += a1.z * w; acc[7] += a1.w * w;
            }
        }
    }
    float bv = bias ? __ldg(bias + n0 + nl) : 0.0f;
    int col = n0 + nl;
    #pragma unroll
    for (int i = 0; i < 8; i++) {
        float v = acc[i] + bv;
        if (act) v = fmaxf(v, 0.f);
        __stcg(C + (size_t)(bg * 8 + i) * ldC + col, v);
    }
}

// ---------------- attention energy tile (HFMA2): (b, 256 t's), full 512 h ----------
__device__ void erg_tile(int step, int b, int tbase,
                         const __half2* s_locw2, const float* s_conv, const float* s_v,
                         float* s_dyn) {
    float*   s_dec  = s_dyn;                       // 512
    float*   s_pw   = s_dyn + 512;                 // 286
    float*   s_eacc = s_dyn + 800;                 // 512 (2 halves x 256 t)
    __half2* s_f2   = (__half2*)(s_dyn + 1312);    // [256][17] half2
    int tid = threadIdx.x;
    for (int i = tid; i < Hz; i += NT) s_dec[i] = __ldcg(g_dec + b * Hz + i);
    const float* prev = (step == 0) ? g_att_prev0 : g_att_sum;
    for (int i = tid; i < 256 + KW - 1; i += NT) {
        int gt = tbase + i - (KW / 2);
        s_pw[i] = (gt >= 0 && gt < Tz) ? __ldcg(prev + b * Tz + gt) : 0.0f;
    }
    __syncthreads();
    // f for this thread's t (1 per thread), fp32 then packed to half2 c-pairs
    {
        float f[CCH];
        #pragma unroll
        for (int c = 0; c < CCH; c++) {
            float a = 0.0f;
            #pragma unroll
            for (int k = 0; k < KW; k++) a += s_conv[c * KW + k] * s_pw[tid + k];
            f[c] = a;
        }
        #pragma unroll
        for (int q = 0; q < 16; q++)
            s_f2[tid * 17 + q] = __floats2half2_rn(f[2 * q], f[2 * q + 1]);
    }
    __syncthreads();

    int tp = tid & 127, hh = tid >> 7;
    int t0 = tbase + 2 * tp;
    int hb = hh * 256;
    __half2 f2a[16], f2b[16];
    #pragma unroll
    for (int q = 0; q < 16; q++) {
        f2a[q] = s_f2[(2 * tp) * 17 + q];
        f2b[q] = s_f2[(2 * tp + 1) * 17 + q];
    }
    const float* pmbase = g_pm + (size_t)b * Hz * Tz + t0;
    float acc0 = 0.f, acc1 = 0.f;
    float2 buf[8];
    #pragma unroll
    for (int j = 0; j < 8; j++)
        buf[j] = __ldcs((const float2*)(pmbase + (size_t)(hb + j) * Tz));
    for (int h0 = 0; h0 < 256; h0 += 8) {
        float2 cur[8];
        #pragma unroll
        for (int j = 0; j < 8; j++) cur[j] = buf[j];
        if (h0 + 8 < 256) {
            #pragma unroll
            for (int j = 0; j < 8; j++)
                buf[j] = __ldcs((const float2*)(pmbase + (size_t)(hb + h0 + 8 + j) * Tz));
        }
        #pragma unroll
        for (int j = 0; j < 8; j++) {
            int h = hb + h0 + j;
            const __half2* wh = s_locw2 + h * 16;
            __half2 dA = __float2half2_rn(0.f), dB = dA;
            #pragma unroll
            for (int q = 0; q < 16; q++) {
                __half2 w = wh[q];
                dA = __hfma2(f2a[q], w, dA);
                dB = __hfma2(f2b[q], w, dB);
            }
            float2 da = __half22float2(dA);
            float2 db = __half22float2(dB);
            float base = s_dec[h];
            float vv = s_v[h];
            acc0 += vv * qtanh(cur[j].x + base + (da.x + da.y));
            acc1 += vv * qtanh(cur[j].y + base + (db.x + db.y));
        }
    }
    s_eacc[hh * 256 + 2 * tp]     = acc0;
    s_eacc[hh * 256 + 2 * tp + 1] = acc1;
    __syncthreads();
    if (tid < 256)
        __stcg(g_erg + b * Tz + tbase + tid, s_eacc[tid] + s_eacc[256 + tid]);
    __syncthreads();
}

// ---------------- softmax + half the context for one b ----------------
__device__ void softctx_half(int b, int half, int step, float* s_dyn, const Params& p) {
    float*  s_w    = s_dyn;                 // 512
    float*  s_red  = s_dyn + 512;           // 16
    float4* s_part = (float4*)(s_dyn + 528); // [4][64] float4
    int tid = threadIdx.x;
    int len = g_len[b];
    float e0 = __ldcg(g_erg + b * Tz + tid);
    float e1 = __ldcg(g_erg + b * Tz + 256 + tid);
    if (tid >= len) e0 = -1e30f;
    if (tid + 256 >= len) e1 = -1e30f;
    float m = fmaxf(e0, e1);
    #pragma unroll
    for (int o = 16; o; o >>= 1) m = fmaxf(m, __shfl_xor_sync(0xffffffffu, m, o));
    if ((tid & 31) == 0) s_red[tid >> 5] = m;
    __syncthreads();
    if (tid == 0) {
        float mm = s_red[0];
        #pragma unroll
        for (int j = 1; j < 8; j++) mm = fmaxf(mm, s_red[j]);
        s_red[8] = mm;
    }
    __syncthreads();
    float mall = s_red[8];
    float p0 = __expf(e0 - mall), p1 = __expf(e1 - mall);
    float s = p0 + p1;
    #pragma unroll
    for (int o = 16; o; o >>= 1) s += __shfl_xor_sync(0xffffffffu, s, o);
    __syncthreads();
    if ((tid & 31) == 0) s_red[tid >> 5] = s;
    __syncthreads();
    if (tid == 0) {
        float ss = 0.f;
        #pragma unroll
        for (int j = 0; j < 8; j++) ss += s_red[j];
        s_red[8] = ss;
    }
    __syncthreads();
    float inv = __fdividef(1.0f, s_red[8]);
    float w0 = p0 * inv, w1 = p1 * inv;
    s_w[tid] = w0; s_w[tid + 256] = w1;
    int tg = half * 256 + tid;
    float wmine = half ? w1 : w0;
    __stcg(g_att_sum + b * Tz + tg, __ldcg(g_att_sum + b * Tz + tg) + wmine);
    p.attw[(size_t)b * Tz * Tz + (size_t)tg * Tz + step] = wmine;
    __syncthreads();
    // context: this half owns channels [half*256, half*256+256); thread = 4 channels, t strided
    int ss4 = tid & 63, g = tid >> 6;
    const float4* eb = (const float4*)(p.enc + (size_t)b * Tz * Cz + half * 256 + ss4 * 4);
    float4 acc = make_float4(0.f, 0.f, 0.f, 0.f);
    for (int tq = g; tq < Tz; tq += 32) {
        float4 e[8]; float wv[8];
        #pragma unroll
        for (int j = 0; j < 8; j++) e[j] = __ldcs(eb + (size_t)(tq + 4 * j) * (Cz / 4));
        #pragma unroll
        for (int j = 0; j < 8; j++) wv[j] = s_w[tq + 4 * j];
        #pragma unroll
        for (int j = 0; j < 8; j++) {
            acc.x += wv[j] * e[j].x; acc.y += wv[j] * e[j].y;
            acc.z += wv[j] * e[j].z; acc.w += wv[j] * e[j].w;
        }
    }
    s_part[g * 64 + ss4] = acc;
    __syncthreads();
    if (tid < 64) {
        float4 r = s_part[tid];
        #pragma unroll
        for (int g2 = 1; g2 < 4; g2++) {
            float4 q = s_part[g2 * 64 + tid];
            r.x += q.x; r.y += q.y; r.z += q.z; r.w += q.w;
        }
        __stcg((float4*)(g_attc + b * Cz + half * 256) + tid, r);
    }
    __syncthreads();
}

// ---------------- GRU gate combine (gi2 optional second partial) ----------------
__device__ void comb_phase(const float* gi, const float* gi2, const float* gh, float* h) {
    int idx = blockIdx.x * NT + threadIdx.x;
    if (idx < Bz * Hz) {
        int b = idx >> 9, n = idx & 511;
        const float* gib = gi + (size_t)b * G3H;
        const float* ghb = gh + (size_t)b * G3H;
        float i0 = __ldcg(gib + n), i1 = __ldcg(gib + 512 + n), i2 = __ldcg(gib + 1024 + n);
        if (gi2) {
            const float* g2 = gi2 + (size_t)b * G3H;
            i0 += __ldcg(g2 + n); i1 += __ldcg(g2 + 512 + n); i2 += __ldcg(g2 + 1024 + n);
        }
        float r  = fsigm(i0 + __ldcg(ghb + n));
        float z  = fsigm(i1 + __ldcg(ghb + 512 + n));
        float nn = ftanh(i2 + r * __ldcg(ghb + 1024 + n));
        float hv = __ldcg(h + idx);
        __stcg(h + idx, (1.0f - z) * nn + z * hv);
    }
}

// ---------------- out finisher: write out(tstep) = bias + sum(partials) ----------
__device__ void outfin_block(int tstep, const Params& p) {
    for (int i = threadIdx.x; i < Bz * DRF; i += NT) {
        int b = i / DRF, n = i - b * DRF;
        float v = __ldg(p.out_b + n)
                + __ldcg(g_opart + i)
                + __ldcg(g_opart + Bz * DRF + i)
                + __ldcg(g_opart + 2 * Bz * DRF + i)
                + __ldcg(g_opart + 3 * Bz * DRF + i);
        p.outp[(size_t)b * 81920 + (size_t)(n >> 1) * 1024 + 2 * tstep + (n & 1)] = v;
    }
}

// ---------------- the persistent decoder (graph node 3) ----------------
__global__ __launch_bounds__(NT, 1) void decoder_kernel(Params p) {
    extern __shared__ float sm[];
    __half2* s_locw2 = (__half2*)sm;          // 512*16 half2 = 32 KB (8192 floats)
    float* s_conv = sm + 8192;                // 1024 (992 used)
    float* s_v    = sm + 8192 + 1024;         // 512
    float* s_dyn  = s_v + 512;                // 6144 floats (24 KB)
    float* sA = s_dyn;                        // 4096
    float* sW = s_dyn + 4096;                 // 2048
    int tid = threadIdx.x;
    for (int i = tid; i < Hz * CCH / 2; i += NT) {
        // pack c-pairs: s_locw2[h*16+q] = (w[h][2q], w[h][2q+1])
        int h = i >> 4, q = i & 15;
        s_locw2[i] = __floats2half2_rn(p.att_loc_w[h * CCH + 2 * q],
                                       p.att_loc_w[h * CCH + 2 * q + 1]);
    }
    for (int i = tid; i < CCH * KW; i += NT) s_conv[i] = p.att_conv_w[i];
    for (int i = tid; i < Hz;       i += NT) s_v[i] = p.att_v_w[i];
    __syncthreads();

    unsigned bno = 0;
    for (int t = 0; t < Tz; t++) {
        // ---- phase B: erg (128) + x1 (8) + outfin(t-1) (1) = 137 units ----
        for (int w = blockIdx.x; w < 137; w += NB) {
            if (w < 128)
                erg_tile(t, w >> 1, (w & 1) * 256, s_locw2, s_conv, s_v, s_dyn);
            else if (w < 136)
                gemv32(sA, sW, 0, 0, 0, PINK, p.pn_w1, PINK, 0,
                       p.pn_b1, (w - 128) * 32, 1, g_x1, PINNER, 1, p.out_b);
            else if (t > 0)
                outfin_block(t - 1, p);
        }
        gridbar(bno);
        // ---- phase C: softmax/context halves (128) + x2 (16) = 144 units ----
        for (int w = blockIdx.x; w < 144; w += NB) {
            if (w < 128)
                softctx_half(w >> 1, w & 1, t, s_dyn, p);
            else
                gemv32(sA, sW, g_x1, PINNER, 0, PINNER, p.pn_w2, PINNER, 0,
                       p.pn_b2, (w - 128) * 32, 1, g_x2, Hz, 0, 0);
        }
        gridbar(bno);
        // ---- phase D: gi0 partials (x2 part 48, attc part 48) ----
        for (int w = blockIdx.x; w < 96; w += NB) {
            if (w < 48)
                gemv32(sA, sW, g_x2, Hz, 0, Hz, p.g0_wih, Hz + Cz, 0,
                       p.g0_bih, w * 32, 0, g_gi0, G3H, 0, 0);
            else
                gemv32(sA, sW, g_attc, Cz, 0, Cz, p.g0_wih, Hz + Cz, Hz,
                       0, (w - 48) * 32, 0, g_gi0b, G3H, 0, 0);
        }
        gridbar(bno);
        // ---- phase E: comb0 ----
        comb_phase(g_gi0, g_gi0b, g_gh0, g_h0);
        gridbar(bno);
        // ---- phase F: gi1 K-split (2 x 48 = 96 units, K=256 each) ----
        for (int w = blockIdx.x; w < 96; w += NB) {
            if (w < 48)
                gemv32(sA, sW, g_h0, Hz, 0, 256, p.g1_wih, Hz, 0,
                       p.g1_bih, w * 32, 0, g_gi1, G3H, 0, 0);
            else
                gemv32(sA, sW, g_h0, Hz, 256, 256, p.g1_wih, Hz, 256,
                       0, (w - 48) * 32, 0, g_gi1b, G3H, 0, 0);
        }
        gridbar(bno);
        // ---- phase G: comb1 ----
        comb_phase(g_gi1, g_gi1b, g_gh1, g_h1);
        gridbar(bno);
        // ---- phase H': out partials (20) + dec (16) + gh0 (48) + gh1 (48) = 132 ----
        for (int w = blockIdx.x; w < 132; w += NB) {
            if (w < 20) {
                int kc = w / 5, nt = w % 5;
                const float* A = (kc < 2) ? g_h1 : g_attc;
                int akoff = (kc & 1) * 256;
                gemv32(sA, sW, A, Hz, akoff, 256, p.out_w, Hz + Cz, kc * 256,
                       0, nt * 32, 0, g_opart + kc * Bz * DRF, DRF, 0, 0);
            } else if (w < 36) {
                gemv32(sA, sW, g_h0, Hz, 0, Hz, p.att_dec_w, Hz, 0,
                       0, (w - 20) * 32, 0, g_dec, Hz, 0, 0);
            } else if (w < 84) {
                gemv32(sA, sW, g_h0, Hz, 0, Hz, p.g0_whh, Hz, 0,
                       p.g0_bhh, (w - 36) * 32, 0, g_gh0, G3H, 0, 0);
            } else {
                gemv32(sA, sW, g_h1, Hz, 0, Hz, p.g1_whh, Hz, 0,
                       p.g1_bhh, (w - 84) * 32, 0, g_gh1, G3H, 0, 0);
            }
        }
        gridbar(bno);
    }
    // final out(t=511), grid-wide
    for (int i = blockIdx.x * NT + tid; i < Bz * DRF; i += NB * NT) {
        int b = i / DRF, n = i - b * DRF;
        float v = __ldg(p.out_b + n)
                + __ldcg(g_opart + i)
                + __ldcg(g_opart + Bz * DRF + i)
                + __ldcg(g_opart + 2 * Bz * DRF + i)
                + __ldcg(g_opart + 3 * Bz * DRF + i);
        p.outp[(size_t)b * 81920 + (size_t)(n >> 1) * 1024 + 2 * 511 + (n & 1)] = v;
    }
}

// ---------------- host ----------------
extern "C" void kernel_launch(void* const* d_in, const int* in_sizes, int n_in,
                              void* d_out, int out_size) {
    const float* enc       = (const float*)d_in[0];
    const int*   data_len  = (const int*)  d_in[1];
    Params p;
    p.enc        = enc;
    p.pn_w1      = (const float*)d_in[2];
    p.pn_b1      = (const float*)d_in[3];
    p.pn_w2      = (const float*)d_in[4];
    p.pn_b2      = (const float*)d_in[5];
    const float* att_enc_w = (const float*)d_in[6];
    const float* att_enc_b = (const float*)d_in[7];
    p.att_dec_w  = (const float*)d_in[8];
    p.att_conv_w = (const float*)d_in[9];
    p.att_loc_w  = (const float*)d_in[10];
    p.att_v_w    = (const float*)d_in[11];
    p.g0_wih     = (const float*)d_in[13];
    p.g0_whh     = (const float*)d_in[14];
    p.g0_bih     = (const float*)d_in[15];
    p.g0_bhh     = (const float*)d_in[16];
    p.g1_wih     = (const float*)d_in[17];
    p.g1_whh     = (const float*)d_in[18];
    p.g1_bih     = (const float*)d_in[19];
    p.g1_bhh     = (const float*)d_in[20];
    p.out_w      = (const float*)d_in[21];
    p.out_b      = (const float*)d_in[22];
    p.outp = (float*)d_out;                           // (B, 80, 1024)
    p.attw = (float*)d_out + (size_t)Bz * 80 * 1024;  // (B, T, T)

    const int smem_bytes = (8192 + 1024 + 512 + 6144) * 4;   // 63488
    cudaFuncSetAttribute(decoder_kernel,
                         cudaFuncAttributeMaxDynamicSharedMemorySize, smem_bytes);

    reset_kernel<<<64, 512>>>(data_len, p.out_b, p.g0_bhh, p.g1_bhh);
    pm_kernel<<<dim3(Tz / 64, Hz / 64, Bz), 256>>>(enc, att_enc_w, att_enc_b);
    decoder_kernel<<<NB, NT, smem_bytes>>>(p);
}

// round 12
// speedup vs baseline: 3.2577x; 1.2345x over previous
#include <cuda_runtime.h>
#include <cuda_fp16.h>

#define NB   148
#define NT   256
#define Bz   64
#define Tz   512
#define Cz   512
#define Hz   512
#define PINK 160
#define PINNER 256
#define CCH  32
#define KW   31
#define DRF  160
#define G3H  1536

// ---------------- scratch (static device globals; no allocation) ----------------
__device__ __align__(128) __half g_pmh[(size_t)Bz * Tz * Hz];   // pm fp16: [b][t][h]
__device__ float g_h0[Bz * Hz];
__device__ float g_h1[Bz * Hz];
__device__ float g_att_sum[Bz * Tz];
__device__ float g_att_prev0[Bz * Tz];
__device__ int   g_len[Bz];
__device__ float g_dec[Bz * Hz];
__device__ float g_x1[Bz * PINNER];
__device__ float g_x2[Bz * Hz];
__device__ float g_attc[Bz * Cz];
__device__ float g_erg[Bz * Tz];
__device__ float g_gi0[Bz * G3H];
__device__ float g_gi0b[Bz * G3H];
__device__ float g_gh0[Bz * G3H];
__device__ float g_gi1[Bz * G3H];
__device__ float g_gi1b[Bz * G3H];
__device__ float g_gh1[Bz * G3H];
__device__ float g_opart[4 * Bz * DRF];       // out-layer K-chunk partial sums
__device__ unsigned g_barctr;

struct Params {
    const float *enc;
    const float *pn_w1, *pn_b1, *pn_w2, *pn_b2;
    const float *att_dec_w, *att_conv_w, *att_loc_w, *att_v_w;
    const float *g0_wih, *g0_whh, *g0_bih, *g0_bhh;
    const float *g1_wih, *g1_whh, *g1_bih, *g1_bhh;
    const float *out_w, *out_b;
    float *outp, *attw;
};

// ---------------- math helpers ----------------
__device__ __forceinline__ float ftanh(float x) {        // precise (GRU path)
    float ax = fabsf(x);
    float e  = __expf(-2.0f * ax);
    float r  = __fdividef(1.0f - e, 1.0f + e);
    return copysignf(r, x);
}
__device__ __forceinline__ float fsigm(float x) {
    return __fdividef(1.0f, 1.0f + __expf(-x));
}
__device__ __forceinline__ float qtanh(float x) {        // fast (attention energy only)
    float r;
    asm("tanh.approx.f32 %0, %1;" : "=f"(r) : "f"(x));
    return r;
}
// m16n8k16 fp16 mma, fp32 accum (canonical Ampere+ fragment layout)
__device__ __forceinline__ void mma16816(float& d0, float& d1, float& d2, float& d3,
        unsigned a0, unsigned a1, unsigned a2, unsigned a3, unsigned b0, unsigned b1) {
    asm("mma.sync.aligned.m16n8k16.row.col.f32.f16.f16.f32 "
        "{%0,%1,%2,%3},{%4,%5,%6,%7},{%8,%9},{%0,%1,%2,%3};"
        : "+f"(d0), "+f"(d1), "+f"(d2), "+f"(d3)
        : "r"(a0), "r"(a1), "r"(a2), "r"(a3), "r"(b0), "r"(b1));
}

// ---------------- software grid barrier (all NB blocks co-resident) ----------------
__device__ __forceinline__ void gridbar(unsigned& bno) {
    __threadfence();
    __syncthreads();
    bno++;
    if (threadIdx.x == 0) {
        atomicAdd(&g_barctr, 1u);
        unsigned target = bno * NB;
        volatile unsigned* ctr = &g_barctr;
        while (*ctr < target) __nanosleep(32);
    }
    __syncthreads();
}

// ---------------- reset (graph node 1) ----------------
__global__ void reset_kernel(const int* __restrict__ dl, const float* __restrict__ outb,
                             const float* __restrict__ bhh0, const float* __restrict__ bhh1) {
    int idx = blockIdx.x * blockDim.x + threadIdx.x;   // 64*512 = 32768
    int b = idx >> 9, t = idx & 511;
    int len = dl[b] >> 1;
    g_att_sum[idx]   = 0.0f;
    g_att_prev0[idx] = (t < len) ? (1.0f / (float)len) : 0.0f;
    g_h0[idx] = 0.0f;
    g_h1[idx] = 0.0f;
    g_dec[idx] = 0.0f;
    if (idx < Bz) g_len[idx] = dl[idx] >> 1;
    if (idx == 0) g_barctr = 0u;
    for (int j = idx; j < 4 * Bz * DRF; j += Bz * Tz)
        g_opart[j] = (j < Bz * DRF) ? -outb[j % DRF] : 0.0f;
    for (int j = idx; j < Bz * G3H; j += Bz * Tz) {     // gh seeded with bhh (t=0: h=0)
        int n = j % G3H;
        g_gh0[j] = bhh0[n];
        g_gh1[j] = bhh1[n];
    }
}

// ------- pm = enc @ att_enc_w^T + b, fp16, stored [b][t][h] (h fast) (node 2) -------
__global__ void pm_kernel(const float* __restrict__ enc,
                          const float* __restrict__ wenc,
                          const float* __restrict__ benc) {
    __shared__ float Es[16][65];
    __shared__ float Ws[16][65];
    int b  = blockIdx.z;
    int to = blockIdx.x * 64;
    int ho = blockIdx.y * 64;
    int tid = threadIdx.x;
    int tx = tid & 15, ty = tid >> 4;   // tx -> h (fast store dim), ty -> t
    float acc[4][4];
    #pragma unroll
    for (int i = 0; i < 4; i++)
        #pragma unroll
        for (int j = 0; j < 4; j++) acc[i][j] = 0.0f;

    for (int k0 = 0; k0 < Cz; k0 += 16) {
        #pragma unroll
        for (int e = 0; e < 4; e++) {
            int i  = tid + e * 256;
            int r  = i >> 4, cc = i & 15;
            Es[cc][r] = enc[((b << 9) + to + r) * Cz + k0 + cc];
            Ws[cc][r] = wenc[(ho + r) * Cz + k0 + cc];
        }
        __syncthreads();
        #pragma unroll
        for (int cc = 0; cc < 16; cc++) {
            float ev[4], wv[4];
            #pragma unroll
            for (int i = 0; i < 4; i++) ev[i] = Es[cc][ty + 16 * i];   // t
            #pragma unroll
            for (int j = 0; j < 4; j++) wv[j] = Ws[cc][tx + 16 * j];   // h
            #pragma unroll
            for (int i = 0; i < 4; i++)
                #pragma unroll
                for (int j = 0; j < 4; j++) acc[i][j] += ev[i] * wv[j];
        }
        __syncthreads();
    }
    #pragma unroll
    for (int i = 0; i < 4; i++) {
        int t = to + ty + 16 * i;
        #pragma unroll
        for (int j = 0; j < 4; j++) {
            int h = ho + tx + 16 * j;
            g_pmh[((size_t)b * Tz + t) * Hz + h] = __float2half(acc[i][j] + __ldg(benc + h));
        }
    }
}

// ---------------- fetch helpers for gemv32 ----------------
__device__ __forceinline__ void fetchA32(float4* rA, const float* A, int ldA, int akoff,
                                         int Klen, int kc0, int lb, int lkq,
                                         int prenetA, const float* outb) {
    #pragma unroll
    for (int q = 0; q < 4; q++) {
        int k = kc0 + lkq * 16 + q * 4;
        if (k < Klen) {
            if (prenetA) {
                float4 ob = *(const float4*)(outb + k);
                float4 p0 = __ldcg((const float4*)(g_opart + 0 * Bz * DRF + lb * DRF + k));
                float4 p1 = __ldcg((const float4*)(g_opart + 1 * Bz * DRF + lb * DRF + k));
                float4 p2 = __ldcg((const float4*)(g_opart + 2 * Bz * DRF + lb * DRF + k));
                float4 p3 = __ldcg((const float4*)(g_opart + 3 * Bz * DRF + lb * DRF + k));
                rA[q].x = ob.x + p0.x + p1.x + p2.x + p3.x;
                rA[q].y = ob.y + p0.y + p1.y + p2.y + p3.y;
                rA[q].z = ob.z + p0.z + p1.z + p2.z + p3.z;
                rA[q].w = ob.w + p0.w + p1.w + p2.w + p3.w;
            } else {
                rA[q] = __ldcg((const float4*)(A + (size_t)lb * ldA + akoff + k));
            }
        }
    }
}
__device__ __forceinline__ void fetchW32(float4* rW, const float* W, int ldW, int wkoff,
                                         int Klen, int kc0, int n0, int wn, int wk8) {
    int k = kc0 + wk8 * 8;
    const float* wr = W + (size_t)(n0 + wn) * ldW + wkoff;
    if (k < Klen)     rW[0] = *(const float4*)(wr + k);
    if (k + 4 < Klen) rW[1] = *(const float4*)(wr + k + 4);
}

// ---------------- gemv32: C[64b x 32n] = act(A[64 x Klen] @ W[n, Klen]^T + bias) ------
__device__ void gemv32(float* sA, float* sW,
        const float* A, int ldA, int akoff, int Klen,
        const float* W, int ldW, int wkoff,
        const float* bias, int n0, int act,
        float* C, int ldC,
        int prenetA, const float* outb)
{
    int tid = threadIdx.x;
    int nl = tid & 31, bg = tid >> 5;        // compute: 32 n lanes, 8 b-groups of 8
    int lb = tid & 63, lkq = tid >> 6;       // A loader
    int wn = tid & 31, wk8 = tid >> 5;       // W loader
    float acc[8];
    #pragma unroll
    for (int i = 0; i < 8; i++) acc[i] = 0.f;

    float4 rA[4], rW[2];
    fetchA32(rA, A, ldA, akoff, Klen, 0, lb, lkq, prenetA, outb);
    fetchW32(rW, W, ldW, wkoff, Klen, 0, n0, wn, wk8);

    for (int k0 = 0; k0 < Klen; k0 += 64) {
        int Kc = Klen - k0; if (Kc > 64) Kc = 64;
        __syncthreads();                     // prior compute done before overwrite
        #pragma unroll
        for (int q = 0; q < 4; q++) {
            int k = lkq * 16 + q * 4;
            if (k < Kc) {
                sA[(k + 0) * 64 + lb] = rA[q].x;
                sA[(k + 1) * 64 + lb] = rA[q].y;
                sA[(k + 2) * 64 + lb] = rA[q].z;
                sA[(k + 3) * 64 + lb] = rA[q].w;
            }
        }
        {
            int k = wk8 * 8;
            if (k < Kc) {
                sW[(k + 0) * 32 + wn] = rW[0].x;
                sW[(k + 1) * 32 + wn] = rW[0].y;
                sW[(k + 2) * 32 + wn] = rW[0].z;
                sW[(k + 3) * 32 + wn] = rW[0].w;
            }
            if (k + 4 < Kc) {
                sW[(k + 4) * 32 + wn] = rW[1].x;
                sW[(k + 5) * 32 + wn] = rW[1].y;
                sW[(k + 6) * 32 + wn] = rW[1].z;
                sW[(k + 7) * 32 + wn] = rW[1].w;
            }
        }
        __syncthreads();
        if (k0 + 64 < Klen) {                // prefetch next chunk during compute
            fetchA32(rA, A, ldA, akoff, Klen, k0 + 64, lb, lkq, prenetA, outb);
            fetchW32(rW, W, ldW, wkoff, Klen, k0 + 64, n0, wn, wk8);
        }
        if (Kc == 64) {
            #pragma unroll 4
            for (int k = 0; k < 64; k++) {
                float w = sW[k * 32 + nl];
                const float4* ap = (const float4*)(sA + k * 64 + bg * 8);
                float4 a0 = ap[0], a1 = ap[1];
                acc[0] += a0.x * w; acc[1] += a0.y * w;
                acc[2] += a0.z * w; acc[3] += a0.w * w;
                acc[4] += a1.x * w; acc[5] += a1.y * w;
                acc[6] += a1.z * w; acc[7] += a1.w * w;
            }
        } else {
            for (int k = 0; k < Kc; k++) {
                float w = sW[k * 32 + nl];
                const float4* ap = (const float4*)(sA + k * 64 + bg * 8);
                float4 a0 = ap[0], a1 = ap[1];
                acc[0] += a0.x * w; acc[1] += a0.y * w;
                acc[2] += a0.z * w; acc[3] += a0.w * w;
                acc[4] += a1.x * w; acc[5] += a1.y * w;
                acc[6] += a1.z * w; acc[7] += a1.w * w;
            }
        }
    }
    float bv = bias ? __ldg(bias + n0 + nl) : 0.0f;
    int col = n0 + nl;
    #pragma unroll
    for (int i = 0; i < 8; i++) {
        float v = acc[i] + bv;
        if (act) v = fmaxf(v, 0.f);
        __stcg(C + (size_t)(bg * 8 + i) * ldC + col, v);
    }
}

// ------- attention energy tile (tensor-core): (b, 256 t's), full 512 h -------
// loc GEMM F[256,32]@locw^T[32,512] via mma.m16n8k16; pm fp16 [b][t][h] added after.
__device__ void erg_tile(int step, int b, int tbase,
                         const unsigned* s_locw2u, const float* s_conv, const float* s_v,
                         float* s_dyn) {
    float*    s_dec = s_dyn;                        // 512 f
    float*    s_pw  = s_dyn + 512;                  // 288 f
    __half2*  s_f2  = (__half2*)(s_dyn + 800);      // [256][17] half2
    unsigned* s_f2u = (unsigned*)s_f2;
    int tid = threadIdx.x;
    for (int i = tid; i < Hz; i += NT) s_dec[i] = __ldcg(g_dec + b * Hz + i);
    const float* prev = (step == 0) ? g_att_prev0 : g_att_sum;
    for (int i = tid; i < 256 + KW - 1; i += NT) {
        int gt = tbase + i - (KW / 2);
        s_pw[i] = (gt >= 0 && gt < Tz) ? __ldcg(prev + b * Tz + gt) : 0.0f;
    }
    __syncthreads();
    {   // conv features for this thread's t; pack to half2 c-pairs
        float f[CCH];
        #pragma unroll
        for (int c = 0; c < CCH; c++) {
            float a = 0.0f;
            #pragma unroll
            for (int k = 0; k < KW; k++) a += s_conv[c * KW + k] * s_pw[tid + k];
            f[c] = a;
        }
        #pragma unroll
        for (int q = 0; q < 16; q++)
            s_f2[tid * 17 + q] = __floats2half2_rn(f[2 * q], f[2 * q + 1]);
    }
    __syncthreads();

    int w = tid >> 5, lane = tid & 31;
    int gid = lane >> 2, q = lane & 3;
    #pragma unroll
    for (int tb = 2 * w; tb < 2 * w + 2; tb++) {
        int t0 = tb * 16;
        // A fragments (rows t0+gid / t0+gid+8; col-pairs q, q+4 (k0-15), q+8, q+12 (k16-31))
        unsigned a0 = s_f2u[(t0 + gid) * 17 + q];
        unsigned a1 = s_f2u[(t0 + gid + 8) * 17 + q];
        unsigned a2 = s_f2u[(t0 + gid) * 17 + q + 4];
        unsigned a3 = s_f2u[(t0 + gid + 8) * 17 + q + 4];
        unsigned e0 = s_f2u[(t0 + gid) * 17 + q + 8];
        unsigned e1 = s_f2u[(t0 + gid + 8) * 17 + q + 8];
        unsigned e2 = s_f2u[(t0 + gid) * 17 + q + 12];
        unsigned e3 = s_f2u[(t0 + gid + 8) * 17 + q + 12];
        const __half* pmA = g_pmh + ((size_t)b * Tz + tbase + t0 + gid) * Hz;
        const __half* pmB = g_pmh + ((size_t)b * Tz + tbase + t0 + gid + 8) * Hz;
        float accA = 0.f, accB = 0.f;
        #pragma unroll 4
        for (int hb = 0; hb < 64; hb++) {
            int h0 = hb * 8;
            int hn = h0 + gid;                       // B col n = gid
            unsigned b0 = s_locw2u[hn * 17 + q];
            unsigned b1 = s_locw2u[hn * 17 + q + 4];
            unsigned b2 = s_locw2u[hn * 17 + q + 8];
            unsigned b3 = s_locw2u[hn * 17 + q + 12];
            float d0 = 0.f, d1 = 0.f, d2 = 0.f, d3 = 0.f;
            mma16816(d0, d1, d2, d3, a0, a1, a2, a3, b0, b1);
            mma16816(d0, d1, d2, d3, e0, e1, e2, e3, b2, b3);
            int ha = h0 + 2 * q;                     // D cols = (2q, 2q+1)
            unsigned pau = __ldcg((const unsigned*)(pmA + ha));
            unsigned pbu = __ldcg((const unsigned*)(pmB + ha));
            float2 paf = __half22float2(*(__half2*)&pau);
            float2 pbf = __half22float2(*(__half2*)&pbu);
            float2 dc = *(const float2*)(s_dec + ha);
            float2 vv = *(const float2*)(s_v + ha);
            accA += vv.x * qtanh(d0 + paf.x + dc.x) + vv.y * qtanh(d1 + paf.y + dc.y);
            accB += vv.x * qtanh(d2 + pbf.x + dc.x) + vv.y * qtanh(d3 + pbf.y + dc.y);
        }
        accA += __shfl_xor_sync(0xffffffffu, accA, 1);
        accA += __shfl_xor_sync(0xffffffffu, accA, 2);
        accB += __shfl_xor_sync(0xffffffffu, accB, 1);
        accB += __shfl_xor_sync(0xffffffffu, accB, 2);
        if (q == 0) {
            __stcg(g_erg + b * Tz + tbase + t0 + gid, accA);
            __stcg(g_erg + b * Tz + tbase + t0 + gid + 8, accB);
        }
    }
    __syncthreads();
}

// ---------------- softmax + half the context for one b ----------------
__device__ void softctx_half(int b, int half, int step, float* s_dyn, const Params& p) {
    float*  s_w    = s_dyn;                 // 512
    float*  s_red  = s_dyn + 512;           // 16
    float4* s_part = (float4*)(s_dyn + 528); // [4][64] float4
    int tid = threadIdx.x;
    int len = g_len[b];
    float e0 = __ldcg(g_erg + b * Tz + tid);
    float e1 = __ldcg(g_erg + b * Tz + 256 + tid);
    if (tid >= len) e0 = -1e30f;
    if (tid + 256 >= len) e1 = -1e30f;
    float m = fmaxf(e0, e1);
    #pragma unroll
    for (int o = 16; o; o >>= 1) m = fmaxf(m, __shfl_xor_sync(0xffffffffu, m, o));
    if ((tid & 31) == 0) s_red[tid >> 5] = m;
    __syncthreads();
    if (tid == 0) {
        float mm = s_red[0];
        #pragma unroll
        for (int j = 1; j < 8; j++) mm = fmaxf(mm, s_red[j]);
        s_red[8] = mm;
    }
    __syncthreads();
    float mall = s_red[8];
    float p0 = __expf(e0 - mall), p1 = __expf(e1 - mall);
    float s = p0 + p1;
    #pragma unroll
    for (int o = 16; o; o >>= 1) s += __shfl_xor_sync(0xffffffffu, s, o);
    __syncthreads();
    if ((tid & 31) == 0) s_red[tid >> 5] = s;
    __syncthreads();
    if (tid == 0) {
        float ss = 0.f;
        #pragma unroll
        for (int j = 0; j < 8; j++) ss += s_red[j];
        s_red[8] = ss;
    }
    __syncthreads();
    float inv = __fdividef(1.0f, s_red[8]);
    float w0 = p0 * inv, w1 = p1 * inv;
    s_w[tid] = w0; s_w[tid + 256] = w1;
    int tg = half * 256 + tid;
    float wmine = half ? w1 : w0;
    __stcg(g_att_sum + b * Tz + tg, __ldcg(g_att_sum + b * Tz + tg) + wmine);
    p.attw[(size_t)b * Tz * Tz + (size_t)tg * Tz + step] = wmine;
    __syncthreads();
    // context: this half owns channels [half*256, half*256+256); thread = 4 channels
    int ss4 = tid & 63, g = tid >> 6;
    const float4* eb = (const float4*)(p.enc + (size_t)b * Tz * Cz + half * 256 + ss4 * 4);
    float4 acc = make_float4(0.f, 0.f, 0.f, 0.f);
    for (int tq = g; tq < Tz; tq += 32) {
        float4 e[8]; float wv[8];
        #pragma unroll
        for (int j = 0; j < 8; j++) e[j] = __ldcs(eb + (size_t)(tq + 4 * j) * (Cz / 4));
        #pragma unroll
        for (int j = 0; j < 8; j++) wv[j] = s_w[tq + 4 * j];
        #pragma unroll
        for (int j = 0; j < 8; j++) {
            acc.x += wv[j] * e[j].x; acc.y += wv[j] * e[j].y;
            acc.z += wv[j] * e[j].z; acc.w += wv[j] * e[j].w;
        }
    }
    s_part[g * 64 + ss4] = acc;
    __syncthreads();
    if (tid < 64) {
        float4 r = s_part[tid];
        #pragma unroll
        for (int g2 = 1; g2 < 4; g2++) {
            float4 qq = s_part[g2 * 64 + tid];
            r.x += qq.x; r.y += qq.y; r.z += qq.z; r.w += qq.w;
        }
        __stcg((float4*)(g_attc + b * Cz + half * 256) + tid, r);
    }
    __syncthreads();
}

// ---------------- GRU gate combine (gi2 optional second partial) ----------------
__device__ void comb_phase(const float* gi, const float* gi2, const float* gh, float* h) {
    int idx = blockIdx.x * NT + threadIdx.x;
    if (idx < Bz * Hz) {
        int b = idx >> 9, n = idx & 511;
        const float* gib = gi + (size_t)b * G3H;
        const float* ghb = gh + (size_t)b * G3H;
        float i0 = __ldcg(gib + n), i1 = __ldcg(gib + 512 + n), i2 = __ldcg(gib + 1024 + n);
        if (gi2) {
            const float* g2 = gi2 + (size_t)b * G3H;
            i0 += __ldcg(g2 + n); i1 += __ldcg(g2 + 512 + n); i2 += __ldcg(g2 + 1024 + n);
        }
        float r  = fsigm(i0 + __ldcg(ghb + n));
        float z  = fsigm(i1 + __ldcg(ghb + 512 + n));
        float nn = ftanh(i2 + r * __ldcg(ghb + 1024 + n));
        float hv = __ldcg(h + idx);
        __stcg(h + idx, (1.0f - z) * nn + z * hv);
    }
}

// ---------------- out finisher: write out(tstep) = bias + sum(partials) ----------
__device__ void outfin_block(int tstep, const Params& p) {
    for (int i = threadIdx.x; i < Bz * DRF; i += NT) {
        int b = i / DRF, n = i - b * DRF;
        float v = __ldg(p.out_b + n)
                + __ldcg(g_opart + i)
                + __ldcg(g_opart + Bz * DRF + i)
                + __ldcg(g_opart + 2 * Bz * DRF + i)
                + __ldcg(g_opart + 3 * Bz * DRF + i);
        p.outp[(size_t)b * 81920 + (size_t)(n >> 1) * 1024 + 2 * tstep + (n & 1)] = v;
    }
}

// ---------------- the persistent decoder (graph node 3) ----------------
__global__ __launch_bounds__(NT, 1) void decoder_kernel(Params p) {
    extern __shared__ float sm[];
    unsigned* s_locw2u = (unsigned*)sm;        // [512][17] half2 = 8704 floats
    float* s_conv = sm + 8704;                 // 1024 (992 used)
    float* s_v    = sm + 8704 + 1024;          // 512
    float* s_dyn  = s_v + 512;                 // 6144 floats
    float* sA = s_dyn;                         // 4096
    float* sW = s_dyn + 4096;                  // 2048
    int tid = threadIdx.x;
    for (int i = tid; i < Hz * 16; i += NT) {
        int h = i >> 4, q = i & 15;            // c-pair q -> (2q, 2q+1)
        __half2 v2 = __floats2half2_rn(p.att_loc_w[h * CCH + 2 * q],
                                       p.att_loc_w[h * CCH + 2 * q + 1]);
        s_locw2u[h * 17 + q] = *(unsigned*)&v2;
    }
    for (int i = tid; i < CCH * KW; i += NT) s_conv[i] = p.att_conv_w[i];
    for (int i = tid; i < Hz;       i += NT) s_v[i] = p.att_v_w[i];
    __syncthreads();

    unsigned bno = 0;
    for (int t = 0; t < Tz; t++) {
        // ---- phase B: erg (128) + x1 (8) + outfin(t-1) (1) = 137 units ----
        for (int w = blockIdx.x; w < 137; w += NB) {
            if (w < 128)
                erg_tile(t, w >> 1, (w & 1) * 256, s_locw2u, s_conv, s_v, s_dyn);
            else if (w < 136)
                gemv32(sA, sW, 0, 0, 0, PINK, p.pn_w1, PINK, 0,
                       p.pn_b1, (w - 128) * 32, 1, g_x1, PINNER, 1, p.out_b);
            else if (t > 0)
                outfin_block(t - 1, p);
        }
        gridbar(bno);
        // ---- phase C: softmax/context halves (128) + x2 (16) = 144 units ----
        for (int w = blockIdx.x; w < 144; w += NB) {
            if (w < 128)
                softctx_half(w >> 1, w & 1, t, s_dyn, p);
            else
                gemv32(sA, sW, g_x1, PINNER, 0, PINNER, p.pn_w2, PINNER, 0,
                       p.pn_b2, (w - 128) * 32, 1, g_x2, Hz, 0, 0);
        }
        gridbar(bno);
        // ---- phase D: gi0 partials (x2 part 48, attc part 48) ----
        for (int w = blockIdx.x; w < 96; w += NB) {
            if (w < 48)
                gemv32(sA, sW, g_x2, Hz, 0, Hz, p.g0_wih, Hz + Cz, 0,
                       p.g0_bih, w * 32, 0, g_gi0, G3H, 0, 0);
            else
                gemv32(sA, sW, g_attc, Cz, 0, Cz, p.g0_wih, Hz + Cz, Hz,
                       0, (w - 48) * 32, 0, g_gi0b, G3H, 0, 0);
        }
        gridbar(bno);
        // ---- phase E: comb0 ----
        comb_phase(g_gi0, g_gi0b, g_gh0, g_h0);
        gridbar(bno);
        // ---- phase F: gi1 K-split (2 x 48 = 96 units, K=256 each) ----
        for (int w = blockIdx.x; w < 96; w += NB) {
            if (w < 48)
                gemv32(sA, sW, g_h0, Hz, 0, 256, p.g1_wih, Hz, 0,
                       p.g1_bih, w * 32, 0, g_gi1, G3H, 0, 0);
            else
                gemv32(sA, sW, g_h0, Hz, 256, 256, p.g1_wih, Hz, 256,
                       0, (w - 48) * 32, 0, g_gi1b, G3H, 0, 0);
        }
        gridbar(bno);
        // ---- phase G: comb1 ----
        comb_phase(g_gi1, g_gi1b, g_gh1, g_h1);
        gridbar(bno);
        // ---- phase H': out partials (20) + dec (16) + gh0 (48) + gh1 (48) = 132 ----
        for (int w = blockIdx.x; w < 132; w += NB) {
            if (w < 20) {
                int kc = w / 5, nt = w % 5;
                const float* A = (kc < 2) ? g_h1 : g_attc;
                int akoff = (kc & 1) * 256;
                gemv32(sA, sW, A, Hz, akoff, 256, p.out_w, Hz + Cz, kc * 256,
                       0, nt * 32, 0, g_opart + kc * Bz * DRF, DRF, 0, 0);
            } else if (w < 36) {
                gemv32(sA, sW, g_h0, Hz, 0, Hz, p.att_dec_w, Hz, 0,
                       0, (w - 20) * 32, 0, g_dec, Hz, 0, 0);
            } else if (w < 84) {
                gemv32(sA, sW, g_h0, Hz, 0, Hz, p.g0_whh, Hz, 0,
                       p.g0_bhh, (w - 36) * 32, 0, g_gh0, G3H, 0, 0);
            } else {
                gemv32(sA, sW, g_h1, Hz, 0, Hz, p.g1_whh, Hz, 0,
                       p.g1_bhh, (w - 84) * 32, 0, g_gh1, G3H, 0, 0);
            }
        }
        gridbar(bno);
    }
    // final out(t=511), grid-wide
    for (int i = blockIdx.x * NT + tid; i < Bz * DRF; i += NB * NT) {
        int b = i / DRF, n = i - b * DRF;
        float v = __ldg(p.out_b + n)
                + __ldcg(g_opart + i)
                + __ldcg(g_opart + Bz * DRF + i)
                + __ldcg(g_opart + 2 * Bz * DRF + i)
                + __ldcg(g_opart + 3 * Bz * DRF + i);
        p.outp[(size_t)b * 81920 + (size_t)(n >> 1) * 1024 + 2 * 511 + (n & 1)] = v;
    }
}

// ---------------- host ----------------
extern "C" void kernel_launch(void* const* d_in, const int* in_sizes, int n_in,
                              void* d_out, int out_size) {
    const float* enc       = (const float*)d_in[0];
    const int*   data_len  = (const int*)  d_in[1];
    Params p;
    p.enc        = enc;
    p.pn_w1      = (const float*)d_in[2];
    p.pn_b1      = (const float*)d_in[3];
    p.pn_w2      = (const float*)d_in[4];
    p.pn_b2      = (const float*)d_in[5];
    const float* att_enc_w = (const float*)d_in[6];
    const float* att_enc_b = (const float*)d_in[7];
    p.att_dec_w  = (const float*)d_in[8];
    p.att_conv_w = (const float*)d_in[9];
    p.att_loc_w  = (const float*)d_in[10];
    p.att_v_w    = (const float*)d_in[11];
    p.g0_wih     = (const float*)d_in[13];
    p.g0_whh     = (const float*)d_in[14];
    p.g0_bih     = (const float*)d_in[15];
    p.g0_bhh     = (const float*)d_in[16];
    p.g1_wih     = (const float*)d_in[17];
    p.g1_whh     = (const float*)d_in[18];
    p.g1_bih     = (const float*)d_in[19];
    p.g1_bhh     = (const float*)d_in[20];
    p.out_w      = (const float*)d_in[21];
    p.out_b      = (const float*)d_in[22];
    p.outp = (float*)d_out;                           // (B, 80, 1024)
    p.attw = (float*)d_out + (size_t)Bz * 80 * 1024;  // (B, T, T)

    const int smem_bytes = (8704 + 1024 + 512 + 6144) * 4;   // 65536
    cudaFuncSetAttribute(decoder_kernel,
                         cudaFuncAttributeMaxDynamicSharedMemorySize, smem_bytes);

    reset_kernel<<<64, 512>>>(data_len, p.out_b, p.g0_bhh, p.g1_bhh);
    pm_kernel<<<dim3(Tz / 64, Hz / 64, Bz), 256>>>(enc, att_enc_w, att_enc_b);
    decoder_kernel<<<NB, NT, smem_bytes>>>(p);
}

// round 13
// speedup vs baseline: 4.0757x; 1.2511x over previous
#include <cuda_runtime.h>
#include <cuda_fp16.h>

#define NB   148
#define NT   256
#define Bz   64
#define Tz   512
#define Cz   512
#define Hz   512
#define PINK 160
#define PINNER 256
#define CCH  32
#define KW   31
#define DRF  160
#define G3H  1536

// ---------------- scratch (static device globals; no allocation) ----------------
__device__ __align__(128) __half g_pmh[(size_t)Bz * Tz * Hz];   // pm fp16: [b][t][h]
__device__ float g_h0[Bz * Hz];
__device__ float g_h1[Bz * Hz];
__device__ float g_att_sum[Bz * Tz];
__device__ float g_att_prev0[Bz * Tz];
__device__ int   g_len[Bz];
__device__ float g_dec[Bz * Hz];
__device__ float g_x1[Bz * PINNER];
__device__ float g_x2[Bz * Hz];
__device__ float g_attc[Bz * Cz];
__device__ float g_erg[Bz * Tz];
__device__ float g_gi0[Bz * G3H];
__device__ float g_gi0b[Bz * G3H];
__device__ float g_gh0[Bz * G3H];
__device__ float g_gi1[Bz * G3H];
__device__ float g_gh1[Bz * G3H];
__device__ float g_opart[4 * Bz * DRF];       // out-layer K-chunk partial sums
__device__ unsigned g_barctr;

// hi/lo fp16 weight copies (prepped once)
__device__ __align__(16) __half g_wdecH[512 * 512],   g_wdecL[512 * 512];
__device__ __align__(16) __half g_w0hhH[G3H * 512],   g_w0hhL[G3H * 512];
__device__ __align__(16) __half g_w1hhH[G3H * 512],   g_w1hhL[G3H * 512];
__device__ __align__(16) __half g_w0ihH[G3H * 1024],  g_w0ihL[G3H * 1024];
__device__ __align__(16) __half g_w1ihH[G3H * 512],   g_w1ihL[G3H * 512];
__device__ __align__(16) __half g_owH[DRF * 1024],    g_owL[DRF * 1024];
// hi/lo fp16 activation copies (written each step by producers)
__device__ __align__(16) __half g_h0H[Bz * Hz],  g_h0L[Bz * Hz];
__device__ __align__(16) __half g_h1H[Bz * Hz],  g_h1L[Bz * Hz];
__device__ __align__(16) __half g_x2H[Bz * Hz],  g_x2L[Bz * Hz];
__device__ __align__(16) __half g_attcH[Bz * Cz], g_attcL[Bz * Cz];

struct Params {
    const float *enc;
    const float *pn_w1, *pn_b1, *pn_w2, *pn_b2;
    const float *att_dec_w, *att_conv_w, *att_loc_w, *att_v_w;
    const float *g0_wih, *g0_whh, *g0_bih, *g0_bhh;
    const float *g1_wih, *g1_whh, *g1_bih, *g1_bhh;
    const float *out_w, *out_b;
    float *outp, *attw;
};

// ---------------- math helpers ----------------
__device__ __forceinline__ float ftanh(float x) {        // precise (GRU path)
    float ax = fabsf(x);
    float e  = __expf(-2.0f * ax);
    float r  = __fdividef(1.0f - e, 1.0f + e);
    return copysignf(r, x);
}
__device__ __forceinline__ float fsigm(float x) {
    return __fdividef(1.0f, 1.0f + __expf(-x));
}
__device__ __forceinline__ float qtanh(float x) {        // fast (attention energy only)
    float r;
    asm("tanh.approx.f32 %0, %1;" : "=f"(r) : "f"(x));
    return r;
}
// m16n8k16 fp16 mma, fp32 accum (canonical Ampere+ fragment layout)
__device__ __forceinline__ void mma16816(float& d0, float& d1, float& d2, float& d3,
        unsigned a0, unsigned a1, unsigned a2, unsigned a3, unsigned b0, unsigned b1) {
    asm("mma.sync.aligned.m16n8k16.row.col.f32.f16.f16.f32 "
        "{%0,%1,%2,%3},{%4,%5,%6,%7},{%8,%9},{%0,%1,%2,%3};"
        : "+f"(d0), "+f"(d1), "+f"(d2), "+f"(d3)
        : "r"(a0), "r"(a1), "r"(a2), "r"(a3), "r"(b0), "r"(b1));
}
// store value + its hi/lo fp16 split (lo scaled by 2048) with L2-visible stores
__device__ __forceinline__ void sthl(__half* ph, __half* pl, size_t idx, float v) {
    __half h = __float2half_rn(v);
    unsigned short hu = __half_as_ushort(h);
    unsigned short lu = __half_as_ushort(__float2half_rn((v - __half2float(h)) * 2048.0f));
    asm volatile("st.global.cg.u16 [%0], %1;" :: "l"(ph + idx), "h"(hu) : "memory");
    asm volatile("st.global.cg.u16 [%0], %1;" :: "l"(pl + idx), "h"(lu) : "memory");
}

// ---------------- software grid barrier (all NB blocks co-resident) ----------------
__device__ __forceinline__ void gridbar(unsigned& bno) {
    __threadfence();
    __syncthreads();
    bno++;
    if (threadIdx.x == 0) {
        atomicAdd(&g_barctr, 1u);
        unsigned target = bno * NB;
        volatile unsigned* ctr = &g_barctr;
        while (*ctr < target) __nanosleep(32);
    }
    __syncthreads();
}

// ---------------- reset (graph node 1) ----------------
__global__ void reset_kernel(const int* __restrict__ dl, const float* __restrict__ outb,
                             const float* __restrict__ bhh0, const float* __restrict__ bhh1) {
    int idx = blockIdx.x * blockDim.x + threadIdx.x;   // 64*512 = 32768
    int b = idx >> 9, t = idx & 511;
    int len = dl[b] >> 1;
    g_att_sum[idx]   = 0.0f;
    g_att_prev0[idx] = (t < len) ? (1.0f / (float)len) : 0.0f;
    g_h0[idx] = 0.0f;
    g_h1[idx] = 0.0f;
    g_dec[idx] = 0.0f;
    if (idx < Bz) g_len[idx] = dl[idx] >> 1;
    if (idx == 0) g_barctr = 0u;
    for (int j = idx; j < 4 * Bz * DRF; j += Bz * Tz)
        g_opart[j] = (j < Bz * DRF) ? -outb[j % DRF] : 0.0f;
    for (int j = idx; j < Bz * G3H; j += Bz * Tz) {     // gh seeded with bhh (t=0: h=0)
        int n = j % G3H;
        g_gh0[j] = bhh0[n];
        g_gh1[j] = bhh1[n];
    }
}

// ---------------- weight hi/lo prep (graph node 2) ----------------
__device__ __forceinline__ void cvt1(const float* __restrict__ s, __half* H, __half* L, int i) {
    float w = s[i];
    __half h = __float2half_rn(w);
    H[i] = h;
    L[i] = __float2half_rn((w - __half2float(h)) * 2048.0f);
}
__global__ void wprep_kernel(const float* __restrict__ wdec, const float* __restrict__ w0hh,
                             const float* __restrict__ w1hh, const float* __restrict__ w0ih,
                             const float* __restrict__ w1ih, const float* __restrict__ ow) {
    int tid = blockIdx.x * blockDim.x + threadIdx.x;
    int stride = gridDim.x * blockDim.x;
    for (int i = tid; i < 512 * 512;   i += stride) cvt1(wdec, g_wdecH, g_wdecL, i);
    for (int i = tid; i < G3H * 512;   i += stride) cvt1(w0hh, g_w0hhH, g_w0hhL, i);
    for (int i = tid; i < G3H * 512;   i += stride) cvt1(w1hh, g_w1hhH, g_w1hhL, i);
    for (int i = tid; i < G3H * 1024;  i += stride) cvt1(w0ih, g_w0ihH, g_w0ihL, i);
    for (int i = tid; i < G3H * 512;   i += stride) cvt1(w1ih, g_w1ihH, g_w1ihL, i);
    for (int i = tid; i < DRF * 1024;  i += stride) cvt1(ow,   g_owH,   g_owL,   i);
}

// ------- pm = enc @ att_enc_w^T + b, fp16, stored [b][t][h] (h fast) (node 3) -------
__global__ void pm_kernel(const float* __restrict__ enc,
                          const float* __restrict__ wenc,
                          const float* __restrict__ benc) {
    __shared__ float Es[16][65];
    __shared__ float Ws[16][65];
    int b  = blockIdx.z;
    int to = blockIdx.x * 64;
    int ho = blockIdx.y * 64;
    int tid = threadIdx.x;
    int tx = tid & 15, ty = tid >> 4;   // tx -> h (fast store dim), ty -> t
    float acc[4][4];
    #pragma unroll
    for (int i = 0; i < 4; i++)
        #pragma unroll
        for (int j = 0; j < 4; j++) acc[i][j] = 0.0f;

    for (int k0 = 0; k0 < Cz; k0 += 16) {
        #pragma unroll
        for (int e = 0; e < 4; e++) {
            int i  = tid + e * 256;
            int r  = i >> 4, cc = i & 15;
            Es[cc][r] = enc[((b << 9) + to + r) * Cz + k0 + cc];
            Ws[cc][r] = wenc[(ho + r) * Cz + k0 + cc];
        }
        __syncthreads();
        #pragma unroll
        for (int cc = 0; cc < 16; cc++) {
            float ev[4], wv[4];
            #pragma unroll
            for (int i = 0; i < 4; i++) ev[i] = Es[cc][ty + 16 * i];   // t
            #pragma unroll
            for (int j = 0; j < 4; j++) wv[j] = Ws[cc][tx + 16 * j];   // h
            #pragma unroll
            for (int i = 0; i < 4; i++)
                #pragma unroll
                for (int j = 0; j < 4; j++) acc[i][j] += ev[i] * wv[j];
        }
        __syncthreads();
    }
    #pragma unroll
    for (int i = 0; i < 4; i++) {
        int t = to + ty + 16 * i;
        #pragma unroll
        for (int j = 0; j < 4; j++) {
            int h = ho + tx + 16 * j;
            g_pmh[((size_t)b * Tz + t) * Hz + h] = __float2half(acc[i][j] + __ldg(benc + h));
        }
    }
}

// ---------------- fetch helpers for gemv32 (fp32 path, small gemvs) ----------------
__device__ __forceinline__ void fetchA32(float4* rA, const float* A, int ldA, int akoff,
                                         int Klen, int kc0, int lb, int lkq,
                                         int prenetA, const float* outb) {
    #pragma unroll
    for (int q = 0; q < 4; q++) {
        int k = kc0 + lkq * 16 + q * 4;
        if (k < Klen) {
            if (prenetA) {
                float4 ob = *(const float4*)(outb + k);
                float4 p0 = __ldcg((const float4*)(g_opart + 0 * Bz * DRF + lb * DRF + k));
                float4 p1 = __ldcg((const float4*)(g_opart + 1 * Bz * DRF + lb * DRF + k));
                float4 p2 = __ldcg((const float4*)(g_opart + 2 * Bz * DRF + lb * DRF + k));
                float4 p3 = __ldcg((const float4*)(g_opart + 3 * Bz * DRF + lb * DRF + k));
                rA[q].x = ob.x + p0.x + p1.x + p2.x + p3.x;
                rA[q].y = ob.y + p0.y + p1.y + p2.y + p3.y;
                rA[q].z = ob.z + p0.z + p1.z + p2.z + p3.z;
                rA[q].w = ob.w + p0.w + p1.w + p2.w + p3.w;
            } else {
                rA[q] = __ldcg((const float4*)(A + (size_t)lb * ldA + akoff + k));
            }
        }
    }
}
__device__ __forceinline__ void fetchW32(float4* rW, const float* W, int ldW, int wkoff,
                                         int Klen, int kc0, int n0, int wn, int wk8) {
    int k = kc0 + wk8 * 8;
    const float* wr = W + (size_t)(n0 + wn) * ldW + wkoff;
    if (k < Klen)     rW[0] = *(const float4*)(wr + k);
    if (k + 4 < Klen) rW[1] = *(const float4*)(wr + k + 4);
}

// ---------------- gemv32 (fp32): C[64b x 32n] = act(A @ W^T + bias) ------
__device__ void gemv32(float* sA, float* sW,
        const float* A, int ldA, int akoff, int Klen,
        const float* W, int ldW, int wkoff,
        const float* bias, int n0, int act,
        float* C, int ldC,
        int prenetA, const float* outb,
        __half* CH, __half* CL)
{
    int tid = threadIdx.x;
    int nl = tid & 31, bg = tid >> 5;
    int lb = tid & 63, lkq = tid >> 6;
    int wn = tid & 31, wk8 = tid >> 5;
    float acc[8];
    #pragma unroll
    for (int i = 0; i < 8; i++) acc[i] = 0.f;

    float4 rA[4], rW[2];
    fetchA32(rA, A, ldA, akoff, Klen, 0, lb, lkq, prenetA, outb);
    fetchW32(rW, W, ldW, wkoff, Klen, 0, n0, wn, wk8);

    for (int k0 = 0; k0 < Klen; k0 += 64) {
        int Kc = Klen - k0; if (Kc > 64) Kc = 64;
        __syncthreads();
        #pragma unroll
        for (int q = 0; q < 4; q++) {
            int k = lkq * 16 + q * 4;
            if (k < Kc) {
                sA[(k + 0) * 64 + lb] = rA[q].x;
                sA[(k + 1) * 64 + lb] = rA[q].y;
                sA[(k + 2) * 64 + lb] = rA[q].z;
                sA[(k + 3) * 64 + lb] = rA[q].w;
            }
        }
        {
            int k = wk8 * 8;
            if (k < Kc) {
                sW[(k + 0) * 32 + wn] = rW[0].x;
                sW[(k + 1) * 32 + wn] = rW[0].y;
                sW[(k + 2) * 32 + wn] = rW[0].z;
                sW[(k + 3) * 32 + wn] = rW[0].w;
            }
            if (k + 4 < Kc) {
                sW[(k + 4) * 32 + wn] = rW[1].x;
                sW[(k + 5) * 32 + wn] = rW[1].y;
                sW[(k + 6) * 32 + wn] = rW[1].z;
                sW[(k + 7) * 32 + wn] = rW[1].w;
            }
        }
        __syncthreads();
        if (k0 + 64 < Klen) {
            fetchA32(rA, A, ldA, akoff, Klen, k0 + 64, lb, lkq, prenetA, outb);
            fetchW32(rW, W, ldW, wkoff, Klen, k0 + 64, n0, wn, wk8);
        }
        for (int k = 0; k < Kc; k++) {
            float w = sW[k * 32 + nl];
            const float4* ap = (const float4*)(sA + k * 64 + bg * 8);
            float4 a0 = ap[0], a1 = ap[1];
            acc[0] += a0.x * w; acc[1] += a0.y * w;
            acc[2] += a0.z * w; acc[3] += a0.w * w;
            acc[4] += a1.x * w; acc[5] += a1.y * w;
            acc[6] += a1.z * w; acc[7] += a1.w * w;
        }
    }
    float bv = bias ? __ldg(bias + n0 + nl) : 0.0f;
    int col = n0 + nl;
    #pragma unroll
    for (int i = 0; i < 8; i++) {
        float v = acc[i] + bv;
        if (act) v = fmaxf(v, 0.f);
        size_t off = (size_t)(bg * 8 + i) * ldC + col;
        __stcg(C + off, v);
        if (CH) sthl(CH, CL, off, v);
    }
}

// ------- mma-gemv (fp16 hi/lo, fp32-equivalent): C[64b x 32n] = A @ W^T + bias -------
__device__ void mmagemv(float* sdyn,
        const __half* __restrict__ AH, const __half* __restrict__ AL,
        int ldA, int akoff, int Klen,
        const __half* __restrict__ WH, const __half* __restrict__ WL,
        int ldW, int wkoff,
        const float* bias, int n0, float* C, int ldC)
{
    unsigned* sAH = (unsigned*)sdyn;          // [64][33]
    unsigned* sAL = sAH + 64 * 33;
    unsigned* sWH = sAL + 64 * 33;            // [32][33]
    unsigned* sWL = sWH + 32 * 33;
    int tid = threadIdx.x;
    int lg = tid & 7, lr = tid >> 3;          // loader: lr 0..31, lg 0..7
    const __half* aBh = AH + akoff + lg * 8;
    const __half* aBl = AL + akoff + lg * 8;
    const __half* wBh = WH + (size_t)(n0 + lr) * ldW + wkoff + lg * 8;
    const __half* wBl = WL + (size_t)(n0 + lr) * ldW + wkoff + lg * 8;

    int wid = tid >> 5, lane = tid & 31;
    int q = lane & 3, gid = lane >> 2;
    int m0 = (wid & 3) * 16;
    int nb0 = (wid >> 2) * 2;                 // n-blocks nb0, nb0+1
    float dh0[4] = {0,0,0,0}, dl0[4] = {0,0,0,0};
    float dh1[4] = {0,0,0,0}, dl1[4] = {0,0,0,0};

    uint4 rA0 = __ldcg((const uint4*)(aBh + (size_t)lr * ldA));
    uint4 rA1 = __ldcg((const uint4*)(aBh + (size_t)(lr + 32) * ldA));
    uint4 rL0 = __ldcg((const uint4*)(aBl + (size_t)lr * ldA));
    uint4 rL1 = __ldcg((const uint4*)(aBl + (size_t)(lr + 32) * ldA));
    uint4 rW  = *(const uint4*)(wBh);
    uint4 rWl = *(const uint4*)(wBl);

    for (int k0 = 0; k0 < Klen; k0 += 64) {
        __syncthreads();
        {
            unsigned* p = sAH + lr * 33 + lg * 4;
            p[0] = rA0.x; p[1] = rA0.y; p[2] = rA0.z; p[3] = rA0.w;
            unsigned* p2 = sAH + (lr + 32) * 33 + lg * 4;
            p2[0] = rA1.x; p2[1] = rA1.y; p2[2] = rA1.z; p2[3] = rA1.w;
            unsigned* p3 = sAL + lr * 33 + lg * 4;
            p3[0] = rL0.x; p3[1] = rL0.y; p3[2] = rL0.z; p3[3] = rL0.w;
            unsigned* p4 = sAL + (lr + 32) * 33 + lg * 4;
            p4[0] = rL1.x; p4[1] = rL1.y; p4[2] = rL1.z; p4[3] = rL1.w;
            unsigned* p5 = sWH + lr * 33 + lg * 4;
            p5[0] = rW.x; p5[1] = rW.y; p5[2] = rW.z; p5[3] = rW.w;
            unsigned* p6 = sWL + lr * 33 + lg * 4;
            p6[0] = rWl.x; p6[1] = rWl.y; p6[2] = rWl.z; p6[3] = rWl.w;
        }
        __syncthreads();
        if (k0 + 64 < Klen) {
            int kn = k0 + 64;
            rA0 = __ldcg((const uint4*)(aBh + kn + (size_t)lr * ldA));
            rA1 = __ldcg((const uint4*)(aBh + kn + (size_t)(lr + 32) * ldA));
            rL0 = __ldcg((const uint4*)(aBl + kn + (size_t)lr * ldA));
            rL1 = __ldcg((const uint4*)(aBl + kn + (size_t)(lr + 32) * ldA));
            rW  = *(const uint4*)(wBh + kn);
            rWl = *(const uint4*)(wBl + kn);
        }
        #pragma unroll
        for (int g = 0; g < 4; g++) {
            int ja = g * 8 + q;
            unsigned aH0 = sAH[(m0 + gid) * 33 + ja];
            unsigned aH1 = sAH[(m0 + gid + 8) * 33 + ja];
            unsigned aH2 = sAH[(m0 + gid) * 33 + ja + 4];
            unsigned aH3 = sAH[(m0 + gid + 8) * 33 + ja + 4];
            unsigned aL0 = sAL[(m0 + gid) * 33 + ja];
            unsigned aL1 = sAL[(m0 + gid + 8) * 33 + ja];
            unsigned aL2 = sAL[(m0 + gid) * 33 + ja + 4];
            unsigned aL3 = sAL[(m0 + gid + 8) * 33 + ja + 4];
            {
                int nr = nb0 * 8 + gid;
                unsigned bH0 = sWH[nr * 33 + ja], bH1 = sWH[nr * 33 + ja + 4];
                unsigned bL0 = sWL[nr * 33 + ja], bL1 = sWL[nr * 33 + ja + 4];
                mma16816(dh0[0], dh0[1], dh0[2], dh0[3], aH0, aH1, aH2, aH3, bH0, bH1);
                mma16816(dl0[0], dl0[1], dl0[2], dl0[3], aH0, aH1, aH2, aH3, bL0, bL1);
                mma16816(dl0[0], dl0[1], dl0[2], dl0[3], aL0, aL1, aL2, aL3, bH0, bH1);
            }
            {
                int nr = (nb0 + 1) * 8 + gid;
                unsigned bH0 = sWH[nr * 33 + ja], bH1 = sWH[nr * 33 + ja + 4];
                unsigned bL0 = sWL[nr * 33 + ja], bL1 = sWL[nr * 33 + ja + 4];
                mma16816(dh1[0], dh1[1], dh1[2], dh1[3], aH0, aH1, aH2, aH3, bH0, bH1);
                mma16816(dl1[0], dl1[1], dl1[2], dl1[3], aH0, aH1, aH2, aH3, bL0, bL1);
                mma16816(dl1[0], dl1[1], dl1[2], dl1[3], aL0, aL1, aL2, aL3, bH0, bH1);
            }
        }
    }
    const float inv = 1.0f / 2048.0f;
    int r0 = m0 + gid;
    {
        int c0 = n0 + nb0 * 8 + 2 * q;
        float b0 = bias ? __ldg(bias + c0) : 0.f;
        float b1 = bias ? __ldg(bias + c0 + 1) : 0.f;
        float2 v;
        v.x = dh0[0] + dl0[0] * inv + b0; v.y = dh0[1] + dl0[1] * inv + b1;
        __stcg((float2*)(C + (size_t)r0 * ldC + c0), v);
        v.x = dh0[2] + dl0[2] * inv + b0; v.y = dh0[3] + dl0[3] * inv + b1;
        __stcg((float2*)(C + (size_t)(r0 + 8) * ldC + c0), v);
    }
    {
        int c0 = n0 + (nb0 + 1) * 8 + 2 * q;
        float b0 = bias ? __ldg(bias + c0) : 0.f;
        float b1 = bias ? __ldg(bias + c0 + 1) : 0.f;
        float2 v;
        v.x = dh1[0] + dl1[0] * inv + b0; v.y = dh1[1] + dl1[1] * inv + b1;
        __stcg((float2*)(C + (size_t)r0 * ldC + c0), v);
        v.x = dh1[2] + dl1[2] * inv + b0; v.y = dh1[3] + dl1[3] * inv + b1;
        __stcg((float2*)(C + (size_t)(r0 + 8) * ldC + c0), v);
    }
}

// ------- attention energy tile (tensor-core): (b, 256 t's), full 512 h -------
__device__ void erg_tile(int step, int b, int tbase,
                         const unsigned* s_locw2u, const float* s_conv, const float* s_v,
                         float* s_dyn) {
    float*    s_dec = s_dyn;                        // 512 f
    float*    s_pw  = s_dyn + 512;                  // 288 f
    __half2*  s_f2  = (__half2*)(s_dyn + 800);      // [256][17] half2
    unsigned* s_f2u = (unsigned*)s_f2;
    int tid = threadIdx.x;
    for (int i = tid; i < Hz; i += NT) s_dec[i] = __ldcg(g_dec + b * Hz + i);
    const float* prev = (step == 0) ? g_att_prev0 : g_att_sum;
    for (int i = tid; i < 256 + KW - 1; i += NT) {
        int gt = tbase + i - (KW / 2);
        s_pw[i] = (gt >= 0 && gt < Tz) ? __ldcg(prev + b * Tz + gt) : 0.0f;
    }
    __syncthreads();
    {   // conv features for this thread's t; pack to half2 c-pairs
        float f[CCH];
        #pragma unroll
        for (int c = 0; c < CCH; c++) {
            float a = 0.0f;
            #pragma unroll
            for (int k = 0; k < KW; k++) a += s_conv[c * KW + k] * s_pw[tid + k];
            f[c] = a;
        }
        #pragma unroll
        for (int q = 0; q < 16; q++)
            s_f2[tid * 17 + q] = __floats2half2_rn(f[2 * q], f[2 * q + 1]);
    }
    __syncthreads();

    int w = tid >> 5, lane = tid & 31;
    int gid = lane >> 2, q = lane & 3;
    #pragma unroll
    for (int tb = 2 * w; tb < 2 * w + 2; tb++) {
        int t0 = tb * 16;
        unsigned a0 = s_f2u[(t0 + gid) * 17 + q];
        unsigned a1 = s_f2u[(t0 + gid + 8) * 17 + q];
        unsigned a2 = s_f2u[(t0 + gid) * 17 + q + 4];
        unsigned a3 = s_f2u[(t0 + gid + 8) * 17 + q + 4];
        unsigned e0 = s_f2u[(t0 + gid) * 17 + q + 8];
        unsigned e1 = s_f2u[(t0 + gid + 8) * 17 + q + 8];
        unsigned e2 = s_f2u[(t0 + gid) * 17 + q + 12];
        unsigned e3 = s_f2u[(t0 + gid + 8) * 17 + q + 12];
        const __half* pmA = g_pmh + ((size_t)b * Tz + tbase + t0 + gid) * Hz;
        const __half* pmB = g_pmh + ((size_t)b * Tz + tbase + t0 + gid + 8) * Hz;
        float accA = 0.f, accB = 0.f;
        #pragma unroll 4
        for (int hb = 0; hb < 64; hb++) {
            int h0 = hb * 8;
            int hn = h0 + gid;
            unsigned b0 = s_locw2u[hn * 17 + q];
            unsigned b1 = s_locw2u[hn * 17 + q + 4];
            unsigned b2 = s_locw2u[hn * 17 + q + 8];
            unsigned b3 = s_locw2u[hn * 17 + q + 12];
            float d0 = 0.f, d1 = 0.f, d2 = 0.f, d3 = 0.f;
            mma16816(d0, d1, d2, d3, a0, a1, a2, a3, b0, b1);
            mma16816(d0, d1, d2, d3, e0, e1, e2, e3, b2, b3);
            int ha = h0 + 2 * q;
            unsigned pau = __ldcg((const unsigned*)(pmA + ha));
            unsigned pbu = __ldcg((const unsigned*)(pmB + ha));
            float2 paf = __half22float2(*(__half2*)&pau);
            float2 pbf = __half22float2(*(__half2*)&pbu);
            float2 dc = *(const float2*)(s_dec + ha);
            float2 vv = *(const float2*)(s_v + ha);
            accA += vv.x * qtanh(d0 + paf.x + dc.x) + vv.y * qtanh(d1 + paf.y + dc.y);
            accB += vv.x * qtanh(d2 + pbf.x + dc.x) + vv.y * qtanh(d3 + pbf.y + dc.y);
        }
        accA += __shfl_xor_sync(0xffffffffu, accA, 1);
        accA += __shfl_xor_sync(0xffffffffu, accA, 2);
        accB += __shfl_xor_sync(0xffffffffu, accB, 1);
        accB += __shfl_xor_sync(0xffffffffu, accB, 2);
        if (q == 0) {
            __stcg(g_erg + b * Tz + tbase + t0 + gid, accA);
            __stcg(g_erg + b * Tz + tbase + t0 + gid + 8, accB);
        }
    }
    __syncthreads();
}

// ---------------- softmax + half the context for one b ----------------
__device__ void softctx_half(int b, int half, int step, float* s_dyn, const Params& p) {
    float*  s_w    = s_dyn;                 // 512
    float*  s_red  = s_dyn + 512;           // 16
    float4* s_part = (float4*)(s_dyn + 528); // [4][64] float4
    int tid = threadIdx.x;
    int len = g_len[b];
    float e0 = __ldcg(g_erg + b * Tz + tid);
    float e1 = __ldcg(g_erg + b * Tz + 256 + tid);
    if (tid >= len) e0 = -1e30f;
    if (tid + 256 >= len) e1 = -1e30f;
    float m = fmaxf(e0, e1);
    #pragma unroll
    for (int o = 16; o; o >>= 1) m = fmaxf(m, __shfl_xor_sync(0xffffffffu, m, o));
    if ((tid & 31) == 0) s_red[tid >> 5] = m;
    __syncthreads();
    if (tid == 0) {
        float mm = s_red[0];
        #pragma unroll
        for (int j = 1; j < 8; j++) mm = fmaxf(mm, s_red[j]);
        s_red[8] = mm;
    }
    __syncthreads();
    float mall = s_red[8];
    float p0 = __expf(e0 - mall), p1 = __expf(e1 - mall);
    float s = p0 + p1;
    #pragma unroll
    for (int o = 16; o; o >>= 1) s += __shfl_xor_sync(0xffffffffu, s, o);
    __syncthreads();
    if ((tid & 31) == 0) s_red[tid >> 5] = s;
    __syncthreads();
    if (tid == 0) {
        float ss = 0.f;
        #pragma unroll
        for (int j = 0; j < 8; j++) ss += s_red[j];
        s_red[8] = ss;
    }
    __syncthreads();
    float inv = __fdividef(1.0f, s_red[8]);
    float w0 = p0 * inv, w1 = p1 * inv;
    s_w[tid] = w0; s_w[tid + 256] = w1;
    int tg = half * 256 + tid;
    float wmine = half ? w1 : w0;
    __stcg(g_att_sum + b * Tz + tg, __ldcg(g_att_sum + b * Tz + tg) + wmine);
    p.attw[(size_t)b * Tz * Tz + (size_t)tg * Tz + step] = wmine;
    __syncthreads();
    // context: this half owns channels [half*256, half*256+256); thread = 4 channels
    int ss4 = tid & 63, g = tid >> 6;
    const float4* eb = (const float4*)(p.enc + (size_t)b * Tz * Cz + half * 256 + ss4 * 4);
    float4 acc = make_float4(0.f, 0.f, 0.f, 0.f);
    for (int tq = g; tq < Tz; tq += 32) {
        float4 e[8]; float wv[8];
        #pragma unroll
        for (int j = 0; j < 8; j++) e[j] = __ldcs(eb + (size_t)(tq + 4 * j) * (Cz / 4));
        #pragma unroll
        for (int j = 0; j < 8; j++) wv[j] = s_w[tq + 4 * j];
        #pragma unroll
        for (int j = 0; j < 8; j++) {
            acc.x += wv[j] * e[j].x; acc.y += wv[j] * e[j].y;
            acc.z += wv[j] * e[j].z; acc.w += wv[j] * e[j].w;
        }
    }
    s_part[g * 64 + ss4] = acc;
    __syncthreads();
    if (tid < 64) {
        float4 r = s_part[tid];
        #pragma unroll
        for (int g2 = 1; g2 < 4; g2++) {
            float4 qq = s_part[g2 * 64 + tid];
            r.x += qq.x; r.y += qq.y; r.z += qq.z; r.w += qq.w;
        }
        size_t base = (size_t)b * Cz + half * 256 + tid * 4;
        __stcg((float4*)(g_attc + base), r);
        sthl(g_attcH, g_attcL, base + 0, r.x);
        sthl(g_attcH, g_attcL, base + 1, r.y);
        sthl(g_attcH, g_attcL, base + 2, r.z);
        sthl(g_attcH, g_attcL, base + 3, r.w);
    }
    __syncthreads();
}

// ---------------- GRU gate combine (gi2 optional second partial) ----------------
__device__ void comb_phase(const float* gi, const float* gi2, const float* gh, float* h,
                           __half* hH, __half* hL) {
    int idx = blockIdx.x * NT + threadIdx.x;
    if (idx < Bz * Hz) {
        int b = idx >> 9, n = idx & 511;
        const float* gib = gi + (size_t)b * G3H;
        const float* ghb = gh + (size_t)b * G3H;
        float i0 = __ldcg(gib + n), i1 = __ldcg(gib + 512 + n), i2 = __ldcg(gib + 1024 + n);
        if (gi2) {
            const float* g2 = gi2 + (size_t)b * G3H;
            i0 += __ldcg(g2 + n); i1 += __ldcg(g2 + 512 + n); i2 += __ldcg(g2 + 1024 + n);
        }
        float r  = fsigm(i0 + __ldcg(ghb + n));
        float z  = fsigm(i1 + __ldcg(ghb + 512 + n));
        float nn = ftanh(i2 + r * __ldcg(ghb + 1024 + n));
        float hv = __ldcg(h + idx);
        float nv = (1.0f - z) * nn + z * hv;
        __stcg(h + idx, nv);
        sthl(hH, hL, idx, nv);
    }
}

// ---------------- out finisher: write out(tstep) = bias + sum(partials) ----------
__device__ void outfin_block(int tstep, const Params& p) {
    for (int i = threadIdx.x; i < Bz * DRF; i += NT) {
        int b = i / DRF, n = i - b * DRF;
        float v = __ldg(p.out_b + n)
                + __ldcg(g_opart + i)
                + __ldcg(g_opart + Bz * DRF + i)
                + __ldcg(g_opart + 2 * Bz * DRF + i)
                + __ldcg(g_opart + 3 * Bz * DRF + i);
        p.outp[(size_t)b * 81920 + (size_t)(n >> 1) * 1024 + 2 * tstep + (n & 1)] = v;
    }
}

// ---------------- the persistent decoder (graph node 4) ----------------
__global__ __launch_bounds__(NT, 1) void decoder_kernel(Params p) {
    extern __shared__ float sm[];
    unsigned* s_locw2u = (unsigned*)sm;        // [512][17] half2 = 8704 floats
    float* s_conv = sm + 8704;                 // 1024 (992 used)
    float* s_v    = sm + 8704 + 1024;          // 512
    float* s_dyn  = s_v + 512;                 // 8192 floats (32 KB)
    float* sA = s_dyn;                         // gemv32: 4096
    float* sW = s_dyn + 4096;                  // gemv32: 2048
    int tid = threadIdx.x;
    for (int i = tid; i < Hz * 16; i += NT) {
        int h = i >> 4, q = i & 15;
        __half2 v2 = __floats2half2_rn(p.att_loc_w[h * CCH + 2 * q],
                                       p.att_loc_w[h * CCH + 2 * q + 1]);
        s_locw2u[h * 17 + q] = *(unsigned*)&v2;
    }
    for (int i = tid; i < CCH * KW; i += NT) s_conv[i] = p.att_conv_w[i];
    for (int i = tid; i < Hz;       i += NT) s_v[i] = p.att_v_w[i];
    __syncthreads();

    unsigned bno = 0;
    for (int t = 0; t < Tz; t++) {
        // ---- phase B: erg (128) + x1 (8) + outfin(t-1) (1) = 137 units ----
        for (int w = blockIdx.x; w < 137; w += NB) {
            if (w < 128)
                erg_tile(t, w >> 1, (w & 1) * 256, s_locw2u, s_conv, s_v, s_dyn);
            else if (w < 136)
                gemv32(sA, sW, 0, 0, 0, PINK, p.pn_w1, PINK, 0,
                       p.pn_b1, (w - 128) * 32, 1, g_x1, PINNER, 1, p.out_b, 0, 0);
            else if (t > 0)
                outfin_block(t - 1, p);
        }
        gridbar(bno);
        // ---- phase C: softmax/context halves (128) + x2 (16, writes hi/lo) ----
        for (int w = blockIdx.x; w < 144; w += NB) {
            if (w < 128)
                softctx_half(w >> 1, w & 1, t, s_dyn, p);
            else
                gemv32(sA, sW, g_x1, PINNER, 0, PINNER, p.pn_w2, PINNER, 0,
                       p.pn_b2, (w - 128) * 32, 1, g_x2, Hz, 0, 0, g_x2H, g_x2L);
        }
        gridbar(bno);
        // ---- phase D: gi0 partials via mma (x2 48 + attc 48) ----
        for (int w = blockIdx.x; w < 96; w += NB) {
            if (w < 48)
                mmagemv(s_dyn, g_x2H, g_x2L, Hz, 0, Hz, g_w0ihH, g_w0ihL, Hz + Cz, 0,
                        p.g0_bih, w * 32, g_gi0, G3H);
            else
                mmagemv(s_dyn, g_attcH, g_attcL, Cz, 0, Cz, g_w0ihH, g_w0ihL, Hz + Cz, Hz,
                        0, (w - 48) * 32, g_gi0b, G3H);
        }
        gridbar(bno);
        // ---- phase E: comb0 ----
        comb_phase(g_gi0, g_gi0b, g_gh0, g_h0, g_h0H, g_h0L);
        gridbar(bno);
        // ---- phase F: gi1 via mma (48, K=512) ----
        for (int w = blockIdx.x; w < 48; w += NB)
            mmagemv(s_dyn, g_h0H, g_h0L, Hz, 0, Hz, g_w1ihH, g_w1ihL, Hz, 0,
                    p.g1_bih, w * 32, g_gi1, G3H);
        gridbar(bno);
        // ---- phase G: comb1 ----
        comb_phase(g_gi1, 0, g_gh1, g_h1, g_h1H, g_h1L);
        gridbar(bno);
        // ---- phase H: out (20) + dec (16) + gh0 (48) + gh1 (48) = 132, all mma ----
        for (int w = blockIdx.x; w < 132; w += NB) {
            if (w < 20) {
                int kc = w / 5, nt = w % 5;
                const __half* AH = (kc < 2) ? g_h1H : g_attcH;
                const __half* AL = (kc < 2) ? g_h1L : g_attcL;
                int akoff = (kc & 1) * 256;
                mmagemv(s_dyn, AH, AL, Hz, akoff, 256, g_owH, g_owL, Hz + Cz, kc * 256,
                        0, nt * 32, g_opart + kc * Bz * DRF, DRF);
            } else if (w < 36) {
                mmagemv(s_dyn, g_h0H, g_h0L, Hz, 0, Hz, g_wdecH, g_wdecL, Hz, 0,
                        0, (w - 20) * 32, g_dec, Hz);
            } else if (w < 84) {
                mmagemv(s_dyn, g_h0H, g_h0L, Hz, 0, Hz, g_w0hhH, g_w0hhL, Hz, 0,
                        p.g0_bhh, (w - 36) * 32, g_gh0, G3H);
            } else {
                mmagemv(s_dyn, g_h1H, g_h1L, Hz, 0, Hz, g_w1hhH, g_w1hhL, Hz, 0,
                        p.g1_bhh, (w - 84) * 32, g_gh1, G3H);
            }
        }
        gridbar(bno);
    }
    // final out(t=511), grid-wide
    for (int i = blockIdx.x * NT + tid; i < Bz * DRF; i += NB * NT) {
        int b = i / DRF, n = i - b * DRF;
        float v = __ldg(p.out_b + n)
                + __ldcg(g_opart + i)
                + __ldcg(g_opart + Bz * DRF + i)
                + __ldcg(g_opart + 2 * Bz * DRF + i)
                + __ldcg(g_opart + 3 * Bz * DRF + i);
        p.outp[(size_t)b * 81920 + (size_t)(n >> 1) * 1024 + 2 * 511 + (n & 1)] = v;
    }
}

// ---------------- host ----------------
extern "C" void kernel_launch(void* const* d_in, const int* in_sizes, int n_in,
                              void* d_out, int out_size) {
    const float* enc       = (const float*)d_in[0];
    const int*   data_len  = (const int*)  d_in[1];
    Params p;
    p.enc        = enc;
    p.pn_w1      = (const float*)d_in[2];
    p.pn_b1      = (const float*)d_in[3];
    p.pn_w2      = (const float*)d_in[4];
    p.pn_b2      = (const float*)d_in[5];
    const float* att_enc_w = (const float*)d_in[6];
    const float* att_enc_b = (const float*)d_in[7];
    p.att_dec_w  = (const float*)d_in[8];
    p.att_conv_w = (const float*)d_in[9];
    p.att_loc_w  = (const float*)d_in[10];
    p.att_v_w    = (const float*)d_in[11];
    p.g0_wih     = (const float*)d_in[13];
    p.g0_whh     = (const float*)d_in[14];
    p.g0_bih     = (const float*)d_in[15];
    p.g0_bhh     = (const float*)d_in[16];
    p.g1_wih     = (const float*)d_in[17];
    p.g1_whh     = (const float*)d_in[18];
    p.g1_bih     = (const float*)d_in[19];
    p.g1_bhh     = (const float*)d_in[20];
    p.out_w      = (const float*)d_in[21];
    p.out_b      = (const float*)d_in[22];
    p.outp = (float*)d_out;                           // (B, 80, 1024)
    p.attw = (float*)d_out + (size_t)Bz * 80 * 1024;  // (B, T, T)

    const int smem_bytes = (8704 + 1024 + 512 + 8192) * 4;   // 73728
    cudaFuncSetAttribute(decoder_kernel,
                         cudaFuncAttributeMaxDynamicSharedMemorySize, smem_bytes);

    reset_kernel<<<64, 512>>>(data_len, p.out_b, p.g0_bhh, p.g1_bhh);
    wprep_kernel<<<512, 256>>>(p.att_dec_w, p.g0_whh, p.g1_whh,
                               p.g0_wih, p.g1_wih, p.out_w);
    pm_kernel<<<dim3(Tz / 64, Hz / 64, Bz), 256>>>(enc, att_enc_w, att_enc_b);
    decoder_kernel<<<NB, NT, smem_bytes>>>(p);
}